// round 11
// baseline (speedup 1.0000x reference)
#include <cuda_runtime.h>
#include <math.h>
#include <stdint.h>

// Problem constants
#define DD   1024          // model dim
#define HH   2048          // expert hidden
#define EE   8             // experts
#define TT   8192          // tokens (B*L = 4*2048)
#define KTOP 2
#define NMOE (TT * KTOP)   // 16384 moe assignments
#define NROWS (NMOE + TT)  // 24576 total grouped rows (moe + shared)

#define XSZ   ((size_t)TT * DD)
#define WSZ   ((size_t)EE * DD * HH)
#define SWSZ  ((size_t)DD * HH)

// ---------------------------------------------------------------------------
// Scratch (static __device__ globals: allocation-free per harness rules)
// ---------------------------------------------------------------------------
__device__ float    g_hidden[(size_t)NROWS * HH];   // tf32-rounded bits (as float)
__device__ float    g_y[(size_t)NMOE * DD];
__device__ uint32_t g_xtf[XSZ];                     // pre-converted tf32 bits
__device__ uint32_t g_w1tf[WSZ];
__device__ uint32_t g_w3tf[WSZ];
__device__ uint32_t g_w2tf[WSZ];
__device__ uint32_t g_sw1tf[SWSZ];
__device__ uint32_t g_sw3tf[SWSZ];
__device__ uint32_t g_sw2tf[SWSZ];
__device__ int   g_count[EE];
__device__ int   g_offs[EE + 1];
__device__ int   g_tok[EE * TT];
__device__ int   g_asg_e[NMOE];
__device__ int   g_asg_pos[NMOE];
__device__ float g_asg_w[NMOE];

// ---------------------------------------------------------------------------
// Helpers
// ---------------------------------------------------------------------------
__device__ __forceinline__ uint32_t f2tf(float f) {
    uint32_t r;
    asm("cvt.rna.tf32.f32 %0, %1;" : "=r"(r) : "f"(f));
    return r;
}

__device__ __forceinline__ void mma8(float c[4], const uint32_t a[4], const uint32_t b[2]) {
    asm volatile(
        "mma.sync.aligned.m16n8k8.row.col.f32.tf32.tf32.f32 "
        "{%0,%1,%2,%3},{%4,%5,%6,%7},{%8,%9},{%0,%1,%2,%3};\n"
        : "+f"(c[0]), "+f"(c[1]), "+f"(c[2]), "+f"(c[3])
        : "r"(a[0]), "r"(a[1]), "r"(a[2]), "r"(a[3]), "r"(b[0]), "r"(b[1]));
}

__device__ __forceinline__ void cp16(uint32_t smem_dst, const void* gmem_src, int src_size) {
    asm volatile("cp.async.ca.shared.global [%0], [%1], 16, %2;"
                 :: "r"(smem_dst), "l"(gmem_src), "r"(src_size));
}
__device__ __forceinline__ void cp_commit() { asm volatile("cp.async.commit_group;"); }
__device__ __forceinline__ void cp_wait1()  { asm volatile("cp.async.wait_group 1;" ::: "memory"); }

__device__ __forceinline__ float silu_f(float v) {
    return v / (1.0f + __expf(-v));
}

// B-tile XOR swizzle: element (k, n) -> word k*STRIDE + (n ^ ((k&3)<<3))
__device__ __forceinline__ int bswz(int k, int n) {
    return (n ^ ((k & 3) << 3));
}

// ---------------------------------------------------------------------------
// K-1: elementwise tf32 pre-conversion (vectorized, grid-stride)
// ---------------------------------------------------------------------------
__global__ void cvt_tf32_kernel(const float4* __restrict__ src,
                                uint4* __restrict__ dst, int n4) {
    int i = blockIdx.x * blockDim.x + threadIdx.x;
    int stride = gridDim.x * blockDim.x;
    for (; i < n4; i += stride) {
        float4 v = src[i];
        uint4 o;
        o.x = f2tf(v.x); o.y = f2tf(v.y); o.z = f2tf(v.z); o.w = f2tf(v.w);
        dst[i] = o;
    }
}

// ---------------------------------------------------------------------------
// K0: zero counts
// ---------------------------------------------------------------------------
__global__ void zero_counts_kernel() {
    if (threadIdx.x < EE) g_count[threadIdx.x] = 0;
}

// ---------------------------------------------------------------------------
// K1: router
// ---------------------------------------------------------------------------
__global__ void router_kernel(const float* __restrict__ x,
                              const float* __restrict__ rw,
                              const float* __restrict__ bias) {
    int warp = threadIdx.x >> 5;
    int lane = threadIdx.x & 31;
    int t = blockIdx.x * 8 + warp;

    const float* xr = x + (size_t)t * DD;
    float xv[32];
#pragma unroll
    for (int i = 0; i < 32; i++) xv[i] = xr[lane + (i << 5)];

    float logit[EE];
#pragma unroll
    for (int e = 0; e < EE; e++) {
        const float* we = rw + e * DD;
        float acc = 0.0f;
#pragma unroll
        for (int i = 0; i < 32; i++) acc += xv[i] * we[lane + (i << 5)];
#pragma unroll
        for (int o = 16; o > 0; o >>= 1) acc += __shfl_xor_sync(0xffffffffu, acc, o);
        logit[e] = acc + bias[e];
    }

    if (lane == 0) {
        int e0 = 0;
#pragma unroll
        for (int e = 1; e < EE; e++) if (logit[e] > logit[e0]) e0 = e;
        int e1 = -1;
#pragma unroll
        for (int e = 0; e < EE; e++) {
            if (e == e0) continue;
            if (e1 < 0 || logit[e] > logit[e1]) e1 = e;
        }
        float l0 = logit[e0], l1 = logit[e1];
        float p1 = expf(l1 - l0);
        float inv = 1.0f / (1.0f + p1);
        float w0 = inv, w1 = p1 * inv;

        int pos0 = atomicAdd(&g_count[e0], 1);
        int pos1 = atomicAdd(&g_count[e1], 1);
        g_tok[e0 * TT + pos0] = t;
        g_tok[e1 * TT + pos1] = t;
        g_asg_e[2 * t]     = e0; g_asg_pos[2 * t]     = pos0; g_asg_w[2 * t]     = w0;
        g_asg_e[2 * t + 1] = e1; g_asg_pos[2 * t + 1] = pos1; g_asg_w[2 * t + 1] = w1;
    }
}

// ---------------------------------------------------------------------------
// K2: prefix offsets
// ---------------------------------------------------------------------------
__global__ void offsets_kernel() {
    if (threadIdx.x == 0 && blockIdx.x == 0) {
        int a = 0;
        for (int e = 0; e < EE; e++) { g_offs[e] = a; a += g_count[e]; }
        g_offs[EE] = a;
    }
}

// ---------------------------------------------------------------------------
// K3: grouped GEMM1 (dual): hidden = silu(X W1) * (X W3), gathered rows.
// K-stage 32 (4 MMA sub-steps per sync), 3-stage cp.async ring with
// prefetch-after-barrier, pre-converted tf32 operands.
// ---------------------------------------------------------------------------
#define A_OFF    0
#define A_WORDS  (128 * 36)                // 128 rows x 32 k, stride 36 (conflict-free)
#define B1_OFF   A_WORDS
#define B1_WORDS (32 * 64)                 // 32 k-rows x 64 n, stride 64 + XOR swizzle
#define B3_OFF   (B1_OFF + B1_WORDS)
#define STG1_WORDS (A_WORDS + 2 * B1_WORDS)   // 8704
#define STG1_BYTES (STG1_WORDS * 4)           // 34816
#define SMEM1_BYTES (3 * STG1_BYTES)          // 104448

__global__ __launch_bounds__(256, 2)
void gemm1_kernel() {
    extern __shared__ uint32_t smemw[];

    int g = blockIdx.z;
    int M, rowbase;
    const int* toks;
    const uint32_t *W1, *W3;
    if (g < EE) {
        M = g_count[g]; rowbase = g_offs[g]; toks = g_tok + g * TT;
        W1 = g_w1tf + (size_t)g * DD * HH; W3 = g_w3tf + (size_t)g * DD * HH;
    } else {
        M = TT; rowbase = NMOE; toks = nullptr;
        W1 = g_sw1tf; W3 = g_sw3tf;
    }
    int bm0 = blockIdx.x * 128;
    if (bm0 >= M) return;
    int n0 = blockIdx.y * 64;

    int tid  = threadIdx.x;
    int lane = tid & 31, wid = tid >> 5;
    int wm = wid & 3, wn = wid >> 2;       // 4x2 warps -> 32x32 per warp (dual)
    int t4 = lane & 3, t8 = lane >> 2;

    float accG[2][4][4] = {}, accU[2][4][4] = {};

    // A: 128 rows x 32 words = 1024 chunks of 16B -> 4 per thread.
    // chunk s: m = s>>3, kq = (s&7)<<2 ; thread's chunks: m = tid>>3 + 32*i
    int m0  = tid >> 3;
    int akq = (tid & 7) << 2;
    const uint32_t* aptr[4];
    int asz[4];
#pragma unroll
    for (int i = 0; i < 4; i++) {
        int gm = bm0 + m0 + 32 * i;
        if (gm < M) {
            int tr = toks ? toks[gm] : gm;
            aptr[i] = g_xtf + (size_t)tr * DD + akq;
            asz[i] = 16;
        } else {
            aptr[i] = g_xtf;
            asz[i] = 0;
        }
    }
    int aoff0 = A_OFF + m0 * 36 + akq;     // +1152*i per chunk row-group

    // B: per matrix 32 rows x 64 words = 512 chunks -> 2 per thread.
    // chunk s: k = s>>4, nq = (s&15)<<2 ; thread's: k = tid>>4 + 16*i (k&3 const)
    int bk0 = tid >> 4;
    int bnq = (tid & 15) << 2;
    const uint32_t* b1p = W1 + (size_t)bk0 * HH + n0 + bnq;
    const uint32_t* b3p = W3 + (size_t)bk0 * HH + n0 + bnq;
    int b1off0 = B1_OFF + bk0 * 64 + bswz(bk0, bnq);   // +1024*i
    int b3off0 = B3_OFF + bk0 * 64 + bswz(bk0, bnq);

    uint32_t sbase = (uint32_t)__cvta_generic_to_shared(smemw);

    const int KB = DD / 32;                // 32 K-tiles

    // prologue: prefetch tiles 0 and 1 (separate commit groups)
#pragma unroll
    for (int p = 0; p < 2; p++) {
        uint32_t sb = sbase + p * STG1_BYTES;
        int k0 = p * 32;
#pragma unroll
        for (int i = 0; i < 4; i++)
            cp16(sb + (aoff0 + 1152 * i) * 4, aptr[i] + k0, asz[i]);
#pragma unroll
        for (int i = 0; i < 2; i++) {
            cp16(sb + (b1off0 + 1024 * i) * 4, b1p + (size_t)(k0 + 16 * i) * HH, 16);
            cp16(sb + (b3off0 + 1024 * i) * 4, b3p + (size_t)(k0 + 16 * i) * HH, 16);
        }
        cp_commit();
    }

    int slot = 0;                           // slot of tile kb in the 3-ring
    for (int kb = 0; kb < KB; kb++) {
        cp_wait1();                         // tile kb landed (kb+1 may fly)
        __syncthreads();                    // publish kb; all done with kb-1

        // prefetch tile kb+2 into slot (kb+2)%3 == slot (kb-1)%3 (safe now)
        if (kb + 2 < KB) {
            int ps = slot + 2; if (ps >= 3) ps -= 3;
            uint32_t sb = sbase + ps * STG1_BYTES;
            int k0 = (kb + 2) * 32;
#pragma unroll
            for (int i = 0; i < 4; i++)
                cp16(sb + (aoff0 + 1152 * i) * 4, aptr[i] + k0, asz[i]);
#pragma unroll
            for (int i = 0; i < 2; i++) {
                cp16(sb + (b1off0 + 1024 * i) * 4, b1p + (size_t)(k0 + 16 * i) * HH, 16);
                cp16(sb + (b3off0 + 1024 * i) * 4, b3p + (size_t)(k0 + 16 * i) * HH, 16);
            }
        }
        cp_commit();                        // commit (possibly empty) keeps accounting

        const uint32_t* stg = smemw + slot * STG1_WORDS;
        const uint32_t* A_  = stg + A_OFF;
        const uint32_t* B1_ = stg + B1_OFF;
        const uint32_t* B3_ = stg + B3_OFF;
        int sx = t4 << 3;

#pragma unroll
        for (int ks = 0; ks < 4; ks++) {
            int kk = ks * 8;
            uint32_t a[2][4];
#pragma unroll
            for (int mi = 0; mi < 2; mi++) {
                int mr = wm * 32 + mi * 16 + t8;
                a[mi][0] = A_[mr * 36 + kk + t4];
                a[mi][1] = A_[(mr + 8) * 36 + kk + t4];
                a[mi][2] = A_[mr * 36 + kk + t4 + 4];
                a[mi][3] = A_[(mr + 8) * 36 + kk + t4 + 4];
            }
            uint32_t b1r[4][2], b3r[4][2];
            int r0 = (kk + t4) * 64;
            int r1 = (kk + t4 + 4) * 64;
#pragma unroll
            for (int nj = 0; nj < 4; nj++) {
                int nc = (wn * 32 + nj * 8 + t8) ^ sx;
                b1r[nj][0] = B1_[r0 + nc];
                b1r[nj][1] = B1_[r1 + nc];
                b3r[nj][0] = B3_[r0 + nc];
                b3r[nj][1] = B3_[r1 + nc];
            }
#pragma unroll
            for (int mi = 0; mi < 2; mi++)
#pragma unroll
                for (int nj = 0; nj < 4; nj++) {
                    mma8(accG[mi][nj], a[mi], b1r[nj]);
                    mma8(accU[mi][nj], a[mi], b3r[nj]);
                }
        }

        slot++; if (slot >= 3) slot -= 3;
    }

    // epilogue: silu(G) * U, rounded to tf32 bits -> g_hidden (feeds gemm2 raw)
#pragma unroll
    for (int mi = 0; mi < 2; mi++) {
#pragma unroll
        for (int h = 0; h < 2; h++) {
            int row = wm * 32 + mi * 16 + t8 + h * 8;
            int grow = bm0 + row;
            if (grow < M) {
                size_t base = (size_t)(rowbase + grow) * HH + n0;
#pragma unroll
                for (int nj = 0; nj < 4; nj++) {
                    int col = wn * 32 + nj * 8 + t4 * 2;
                    float2 st;
                    st.x = __uint_as_float(f2tf(
                        silu_f(accG[mi][nj][h * 2 + 0]) * accU[mi][nj][h * 2 + 0]));
                    st.y = __uint_as_float(f2tf(
                        silu_f(accG[mi][nj][h * 2 + 1]) * accU[mi][nj][h * 2 + 1]));
                    *reinterpret_cast<float2*>(&g_hidden[base + col]) = st;
                }
            }
        }
    }
}

// ---------------------------------------------------------------------------
// K4: grouped GEMM2: y = hidden @ W2. Tile 128x128, K-stage 32, 3-ring.
// ---------------------------------------------------------------------------
#define B2_OFF   A_WORDS
#define B2_WORDS (32 * 128)                // 32 k-rows x 128 n, XOR swizzle
#define STG2_WORDS (A_WORDS + B2_WORDS)    // 8704
#define STG2_BYTES (STG2_WORDS * 4)        // 34816
#define SMEM2_BYTES (3 * STG2_BYTES)       // 104448

__global__ __launch_bounds__(256, 2)
void gemm2_kernel(float* __restrict__ out) {
    extern __shared__ uint32_t smemw[];

    int g = blockIdx.z;
    int M, rowbase;
    const uint32_t* W;
    if (g < EE) {
        M = g_count[g]; rowbase = g_offs[g];
        W = g_w2tf + (size_t)g * HH * DD;
    } else {
        M = TT; rowbase = NMOE; W = g_sw2tf;
    }
    int bm0 = blockIdx.x * 128;
    if (bm0 >= M) return;
    int n0 = blockIdx.y * 128;

    int tid  = threadIdx.x;
    int lane = tid & 31, wid = tid >> 5;
    int wm = wid & 3, wn = wid >> 2;       // warp tile 32 x 64
    int t4 = lane & 3, t8 = lane >> 2;

    float acc[2][8][4] = {};

    // A: 4 chunks per thread (same mapping as gemm1)
    int m0  = tid >> 3;
    int akq = (tid & 7) << 2;
    const float* aptr[4];
    int asz[4];
#pragma unroll
    for (int i = 0; i < 4; i++) {
        int gm = bm0 + m0 + 32 * i;
        if (gm < M) {
            aptr[i] = g_hidden + (size_t)(rowbase + gm) * HH + akq;
            asz[i] = 16;
        } else {
            aptr[i] = g_hidden;
            asz[i] = 0;
        }
    }
    int aoff0 = A_OFF + m0 * 36 + akq;

    // B: 32 rows x 128 words = 1024 chunks -> 4 per thread.
    // chunk s: k = s>>5, nq = (s&31)<<2 ; thread's: k = tid>>5 + 8*i (k&3 const)
    int bk0 = tid >> 5;
    int bnq = (lane) << 2;                 // (s&31)<<2 with s=tid: tid&31 = lane
    const uint32_t* bp = W + (size_t)bk0 * DD + n0 + bnq;
    int boff0 = B2_OFF + bk0 * 128 + bswz(bk0, bnq);   // +1024*i

    uint32_t sbase = (uint32_t)__cvta_generic_to_shared(smemw);

    const int KB = HH / 32;                // 64 K-tiles

#pragma unroll
    for (int p = 0; p < 2; p++) {
        uint32_t sb = sbase + p * STG2_BYTES;
        int k0 = p * 32;
#pragma unroll
        for (int i = 0; i < 4; i++)
            cp16(sb + (aoff0 + 1152 * i) * 4, aptr[i] + k0, asz[i]);
#pragma unroll
        for (int i = 0; i < 4; i++)
            cp16(sb + (boff0 + 1024 * i) * 4, bp + (size_t)(k0 + 8 * i) * DD, 16);
        cp_commit();
    }

    int slot = 0;
    for (int kb = 0; kb < KB; kb++) {
        cp_wait1();
        __syncthreads();

        if (kb + 2 < KB) {
            int ps = slot + 2; if (ps >= 3) ps -= 3;
            uint32_t sb = sbase + ps * STG2_BYTES;
            int k0 = (kb + 2) * 32;
#pragma unroll
            for (int i = 0; i < 4; i++)
                cp16(sb + (aoff0 + 1152 * i) * 4, aptr[i] + k0, asz[i]);
#pragma unroll
            for (int i = 0; i < 4; i++)
                cp16(sb + (boff0 + 1024 * i) * 4, bp + (size_t)(k0 + 8 * i) * DD, 16);
        }
        cp_commit();

        const uint32_t* stg = smemw + slot * STG2_WORDS;
        const uint32_t* A_ = stg + A_OFF;
        const uint32_t* B_ = stg + B2_OFF;
        int sx = t4 << 3;

#pragma unroll
        for (int ks = 0; ks < 4; ks++) {
            int kk = ks * 8;
            uint32_t a[2][4];
#pragma unroll
            for (int mi = 0; mi < 2; mi++) {
                int mr = wm * 32 + mi * 16 + t8;
                a[mi][0] = A_[mr * 36 + kk + t4];
                a[mi][1] = A_[(mr + 8) * 36 + kk + t4];
                a[mi][2] = A_[mr * 36 + kk + t4 + 4];
                a[mi][3] = A_[(mr + 8) * 36 + kk + t4 + 4];
            }
            uint32_t br[8][2];
            int r0 = (kk + t4) * 128;
            int r1 = (kk + t4 + 4) * 128;
#pragma unroll
            for (int nj = 0; nj < 8; nj++) {
                int nc = (wn * 64 + nj * 8 + t8) ^ sx;
                br[nj][0] = B_[r0 + nc];
                br[nj][1] = B_[r1 + nc];
            }
#pragma unroll
            for (int mi = 0; mi < 2; mi++)
#pragma unroll
                for (int nj = 0; nj < 8; nj++)
                    mma8(acc[mi][nj], a[mi], br[nj]);
        }

        slot++; if (slot >= 3) slot -= 3;
    }

#pragma unroll
    for (int mi = 0; mi < 2; mi++) {
#pragma unroll
        for (int h = 0; h < 2; h++) {
            int row = wm * 32 + mi * 16 + t8 + h * 8;
            int grow = bm0 + row;
            if (grow < M) {
#pragma unroll
                for (int nj = 0; nj < 8; nj++) {
                    int col = wn * 64 + nj * 8 + t4 * 2;
                    float2 st;
                    st.x = acc[mi][nj][h * 2 + 0];
                    st.y = acc[mi][nj][h * 2 + 1];
                    if (g < EE) {
                        size_t base = (size_t)(rowbase + grow) * DD + n0;
                        *reinterpret_cast<float2*>(&g_y[base + col]) = st;
                    } else {
                        size_t base = (size_t)grow * DD + n0;   // grow == token id
                        *reinterpret_cast<float2*>(&out[base + col]) = st;
                    }
                }
            }
        }
    }
}

// ---------------------------------------------------------------------------
// K5: combine: out[t] += w0*y[r0] + w1*y[r1]
// ---------------------------------------------------------------------------
__global__ void combine_kernel(float* __restrict__ out) {
    int t = blockIdx.x;
    int e0 = g_asg_e[2 * t],     e1 = g_asg_e[2 * t + 1];
    int r0 = g_offs[e0] + g_asg_pos[2 * t];
    int r1 = g_offs[e1] + g_asg_pos[2 * t + 1];
    float w0 = g_asg_w[2 * t], w1 = g_asg_w[2 * t + 1];

    int c = threadIdx.x * 4;
    float4 o  = *reinterpret_cast<const float4*>(out + (size_t)t * DD + c);
    float4 y0 = *reinterpret_cast<const float4*>(g_y + (size_t)r0 * DD + c);
    float4 y1 = *reinterpret_cast<const float4*>(g_y + (size_t)r1 * DD + c);
    o.x += w0 * y0.x + w1 * y1.x;
    o.y += w0 * y0.y + w1 * y1.y;
    o.z += w0 * y0.z + w1 * y1.z;
    o.w += w0 * y0.w + w1 * y1.w;
    *reinterpret_cast<float4*>(out + (size_t)t * DD + c) = o;
}

// ---------------------------------------------------------------------------
// Launch
// ---------------------------------------------------------------------------
extern "C" void kernel_launch(void* const* d_in, const int* in_sizes, int n_in,
                              void* d_out, int out_size) {
    const float* x    = (const float*)d_in[0];
    const float* rw   = (const float*)d_in[1];
    const float* bias = (const float*)d_in[2];
    const float* w1   = (const float*)d_in[3];
    const float* w3   = (const float*)d_in[4];
    const float* w2   = (const float*)d_in[5];
    const float* sw1  = (const float*)d_in[6];
    const float* sw3  = (const float*)d_in[7];
    const float* sw2  = (const float*)d_in[8];
    float* out = (float*)d_out;

    cudaFuncSetAttribute(gemm1_kernel, cudaFuncAttributeMaxDynamicSharedMemorySize, SMEM1_BYTES);
    cudaFuncSetAttribute(gemm2_kernel, cudaFuncAttributeMaxDynamicSharedMemorySize, SMEM2_BYTES);

    uint32_t* xtf;   cudaGetSymbolAddress((void**)&xtf,  g_xtf);
    uint32_t* w1tf;  cudaGetSymbolAddress((void**)&w1tf, g_w1tf);
    uint32_t* w3tf;  cudaGetSymbolAddress((void**)&w3tf, g_w3tf);
    uint32_t* w2tf;  cudaGetSymbolAddress((void**)&w2tf, g_w2tf);
    uint32_t* s1tf;  cudaGetSymbolAddress((void**)&s1tf, g_sw1tf);
    uint32_t* s3tf;  cudaGetSymbolAddress((void**)&s3tf, g_sw3tf);
    uint32_t* s2tf;  cudaGetSymbolAddress((void**)&s2tf, g_sw2tf);

    // pre-convert everything to tf32 bits
    cvt_tf32_kernel<<<1792, 256>>>((const float4*)x,   (uint4*)xtf,  (int)(XSZ  / 4));
    cvt_tf32_kernel<<<1792, 256>>>((const float4*)w1,  (uint4*)w1tf, (int)(WSZ  / 4));
    cvt_tf32_kernel<<<1792, 256>>>((const float4*)w3,  (uint4*)w3tf, (int)(WSZ  / 4));
    cvt_tf32_kernel<<<1792, 256>>>((const float4*)w2,  (uint4*)w2tf, (int)(WSZ  / 4));
    cvt_tf32_kernel<<<1792, 256>>>((const float4*)sw1, (uint4*)s1tf, (int)(SWSZ / 4));
    cvt_tf32_kernel<<<1792, 256>>>((const float4*)sw3, (uint4*)s3tf, (int)(SWSZ / 4));
    cvt_tf32_kernel<<<1792, 256>>>((const float4*)sw2, (uint4*)s2tf, (int)(SWSZ / 4));

    zero_counts_kernel<<<1, 32>>>();
    router_kernel<<<TT / 8, 256>>>(x, rw, bias);
    offsets_kernel<<<1, 32>>>();

    dim3 grid1(TT / 128, HH / 64, EE + 1);
    gemm1_kernel<<<grid1, 256, SMEM1_BYTES>>>();

    dim3 grid2(TT / 128, DD / 128, EE + 1);
    gemm2_kernel<<<grid2, 256, SMEM2_BYTES>>>(out);

    combine_kernel<<<TT, 256>>>(out);
}

// round 13
// speedup vs baseline: 1.7380x; 1.7380x over previous
#include <cuda_runtime.h>
#include <cuda_fp16.h>
#include <math.h>
#include <stdint.h>

// Problem constants
#define DD   1024
#define HH   2048
#define EE   8
#define TT   8192
#define KTOP 2
#define NMOE (TT * KTOP)
#define NROWS (NMOE + TT)

#define XSZ   ((size_t)TT * DD)
#define WSZ   ((size_t)EE * DD * HH)
#define SWSZ  ((size_t)DD * HH)

// ---------------------------------------------------------------------------
// Scratch (static __device__ globals)
// ---------------------------------------------------------------------------
__device__ __half g_hidden[(size_t)NROWS * HH];   // fp16 activations
__device__ float  g_y[(size_t)NMOE * DD];
__device__ __half g_xh[XSZ];                      // x fp16, [T][D]
__device__ __half g_w1h[WSZ];                     // W1^T fp16: [E][H][D]
__device__ __half g_w3h[WSZ];
__device__ __half g_w2h[WSZ];                     // W2^T fp16: [E][D][H]
__device__ __half g_sw1h[SWSZ];
__device__ __half g_sw3h[SWSZ];
__device__ __half g_sw2h[SWSZ];
__device__ int   g_count[EE];
__device__ int   g_offs[EE + 1];
__device__ int   g_tok[EE * TT];
__device__ int   g_asg_e[NMOE];
__device__ int   g_asg_pos[NMOE];
__device__ float g_asg_w[NMOE];

// ---------------------------------------------------------------------------
// Helpers
// ---------------------------------------------------------------------------
__device__ __forceinline__ void mma16(float c[4], const uint32_t a[4], const uint32_t b[2]) {
    asm volatile(
        "mma.sync.aligned.m16n8k16.row.col.f32.f16.f16.f32 "
        "{%0,%1,%2,%3},{%4,%5,%6,%7},{%8,%9},{%0,%1,%2,%3};\n"
        : "+f"(c[0]), "+f"(c[1]), "+f"(c[2]), "+f"(c[3])
        : "r"(a[0]), "r"(a[1]), "r"(a[2]), "r"(a[3]), "r"(b[0]), "r"(b[1]));
}

__device__ __forceinline__ void cp16(uint32_t smem_dst, const void* gmem_src, int src_size) {
    asm volatile("cp.async.ca.shared.global [%0], [%1], 16, %2;"
                 :: "r"(smem_dst), "l"(gmem_src), "r"(src_size));
}
__device__ __forceinline__ void cp_commit() { asm volatile("cp.async.commit_group;"); }
__device__ __forceinline__ void cp_wait2()  { asm volatile("cp.async.wait_group 2;" ::: "memory"); }

__device__ __forceinline__ float silu_f(float v) { return v / (1.0f + __expf(-v)); }

// ---------------------------------------------------------------------------
// Prep: x fp32 -> fp16 (vectorized)
// ---------------------------------------------------------------------------
__global__ void cvt_f16_kernel(const float4* __restrict__ src, uint2* __restrict__ dst, int n4) {
    int i = blockIdx.x * blockDim.x + threadIdx.x;
    int stride = gridDim.x * blockDim.x;
    for (; i < n4; i += stride) {
        float4 v = src[i];
        __half2 h0 = __floats2half2_rn(v.x, v.y);
        __half2 h1 = __floats2half2_rn(v.z, v.w);
        uint2 o;
        o.x = *reinterpret_cast<uint32_t*>(&h0);
        o.y = *reinterpret_cast<uint32_t*>(&h1);
        dst[i] = o;
    }
}

// Prep: transpose + fp16 convert: src [K][N] (per blockIdx.z) -> dst [N][K]
__global__ void trans_cvt_h(const float* __restrict__ src, __half* __restrict__ dst,
                            int K, int N) {
    __shared__ float t[32][33];
    size_t eo = (size_t)blockIdx.z * K * N;
    int n0 = blockIdx.x * 32, k0 = blockIdx.y * 32;
    int tx = threadIdx.x & 31, ty = threadIdx.x >> 5;
#pragma unroll
    for (int i = 0; i < 4; i++) {
        int k = k0 + ty + 8 * i;
        t[ty + 8 * i][tx] = src[eo + (size_t)k * N + n0 + tx];
    }
    __syncthreads();
#pragma unroll
    for (int i = 0; i < 4; i++) {
        int n = n0 + ty + 8 * i;
        dst[eo + (size_t)n * K + k0 + tx] = __float2half_rn(t[tx][ty + 8 * i]);
    }
}

// ---------------------------------------------------------------------------
// Routing kernels
// ---------------------------------------------------------------------------
__global__ void zero_counts_kernel() {
    if (threadIdx.x < EE) g_count[threadIdx.x] = 0;
}

__global__ void router_kernel(const float* __restrict__ x, const float* __restrict__ rw,
                              const float* __restrict__ bias) {
    int warp = threadIdx.x >> 5;
    int lane = threadIdx.x & 31;
    int t = blockIdx.x * 8 + warp;

    const float* xr = x + (size_t)t * DD;
    float xv[32];
#pragma unroll
    for (int i = 0; i < 32; i++) xv[i] = xr[lane + (i << 5)];

    float logit[EE];
#pragma unroll
    for (int e = 0; e < EE; e++) {
        const float* we = rw + e * DD;
        float acc = 0.0f;
#pragma unroll
        for (int i = 0; i < 32; i++) acc += xv[i] * we[lane + (i << 5)];
#pragma unroll
        for (int o = 16; o > 0; o >>= 1) acc += __shfl_xor_sync(0xffffffffu, acc, o);
        logit[e] = acc + bias[e];
    }

    if (lane == 0) {
        int e0 = 0;
#pragma unroll
        for (int e = 1; e < EE; e++) if (logit[e] > logit[e0]) e0 = e;
        int e1 = -1;
#pragma unroll
        for (int e = 0; e < EE; e++) {
            if (e == e0) continue;
            if (e1 < 0 || logit[e] > logit[e1]) e1 = e;
        }
        float l0 = logit[e0], l1 = logit[e1];
        float p1 = expf(l1 - l0);
        float inv = 1.0f / (1.0f + p1);
        float w0 = inv, w1 = p1 * inv;

        int pos0 = atomicAdd(&g_count[e0], 1);
        int pos1 = atomicAdd(&g_count[e1], 1);
        g_tok[e0 * TT + pos0] = t;
        g_tok[e1 * TT + pos1] = t;
        g_asg_e[2 * t]     = e0; g_asg_pos[2 * t]     = pos0; g_asg_w[2 * t]     = w0;
        g_asg_e[2 * t + 1] = e1; g_asg_pos[2 * t + 1] = pos1; g_asg_w[2 * t + 1] = w1;
    }
}

__global__ void offsets_kernel() {
    if (threadIdx.x == 0 && blockIdx.x == 0) {
        int a = 0;
        for (int e = 0; e < EE; e++) { g_offs[e] = a; a += g_count[e]; }
        g_offs[EE] = a;
    }
}

// ---------------------------------------------------------------------------
// GEMM1 (dual fp16): hidden = silu(X W1) * (X W3). CTA 128x64(dual), K32 stages.
// A smem: 128 rows x 16 words (32 halfs), stride 20 words (conflict-free).
// B smem (n-major): 64 rows x 16 words, stride 20.
// 4-stage ring, distance-2 prefetch, wait2, one barrier per stage (R9 struct).
// ---------------------------------------------------------------------------
#define A_OFF    0
#define A_WORDS  (128 * 20)                 // 2560
#define B1_OFF   A_WORDS
#define B1_WORDS (64 * 20)                  // 1280
#define B3_OFF   (B1_OFF + B1_WORDS)
#define STG1_WORDS (A_WORDS + 2 * B1_WORDS) // 5120 words = 20480 B
#define STG1_BYTES (STG1_WORDS * 4)
#define SMEM1_BYTES (4 * STG1_BYTES)        // 81920

__global__ __launch_bounds__(256, 2)
void gemm1_kernel() {
    extern __shared__ uint32_t smemw[];

    int g = blockIdx.z;
    int M, rowbase;
    const int* toks;
    const __half *W1H, *W3H;
    if (g < EE) {
        M = g_count[g]; rowbase = g_offs[g]; toks = g_tok + g * TT;
        W1H = g_w1h + (size_t)g * DD * HH; W3H = g_w3h + (size_t)g * DD * HH;
    } else {
        M = TT; rowbase = NMOE; toks = nullptr;
        W1H = g_sw1h; W3H = g_sw3h;
    }
    int bm0 = blockIdx.x * 128;
    if (bm0 >= M) return;
    int n0 = blockIdx.y * 64;

    int tid  = threadIdx.x;
    int lane = tid & 31, wid = tid >> 5;
    int wm = wid & 3, wn = wid >> 2;       // 4x2 warps -> 32x32 per warp (dual)
    int t4 = lane & 3, t8 = lane >> 2;

    float accG[2][4][4] = {}, accU[2][4][4] = {};

    // producer: 1024 chunks (A 512, B1 256, B3 256) -> 4 per thread
    const __half* src[4];
    int sz[4], off[4];
#pragma unroll
    for (int j = 0; j < 4; j++) {
        int c = tid + 256 * j;
        if (c < 512) {
            int row = c >> 2, kw = (c & 3) << 2;        // word offset 0,4,8,12
            int gm = bm0 + row;
            if (gm < M) {
                int tr = toks ? toks[gm] : gm;
                src[j] = g_xh + (size_t)tr * DD + kw * 2; sz[j] = 16;
            } else { src[j] = g_xh; sz[j] = 0; }
            off[j] = A_OFF + row * 20 + kw;
        } else if (c < 768) {
            int n = (c - 512) >> 2, kw = (c & 3) << 2;
            src[j] = W1H + (size_t)(n0 + n) * DD + kw * 2; sz[j] = 16;
            off[j] = B1_OFF + n * 20 + kw;
        } else {
            int n = (c - 768) >> 2, kw = (c & 3) << 2;
            src[j] = W3H + (size_t)(n0 + n) * DD + kw * 2; sz[j] = 16;
            off[j] = B3_OFF + n * 20 + kw;
        }
    }

    uint32_t sbase = (uint32_t)__cvta_generic_to_shared(smemw);

    // prologue: prefetch stages 0, 1
#pragma unroll
    for (int p = 0; p < 2; p++) {
        uint32_t sb = sbase + p * STG1_BYTES;
        int k0 = p * 32;                                // halfs
#pragma unroll
        for (int j = 0; j < 4; j++) cp16(sb + off[j] * 4, src[j] + k0, sz[j]);
        cp_commit();
    }

    const int KB = DD / 32;                             // 32
    for (int kb = 0; kb < KB; kb++) {
        if (kb + 2 < KB) {
            uint32_t sb = sbase + ((kb + 2) & 3) * STG1_BYTES;
            int k0 = (kb + 2) * 32;
#pragma unroll
            for (int j = 0; j < 4; j++) cp16(sb + off[j] * 4, src[j] + k0, sz[j]);
        }
        cp_commit();
        cp_wait2();
        __syncthreads();

        const uint32_t* stg = smemw + (kb & 3) * STG1_WORDS;
        const uint32_t* A_  = stg + A_OFF;
        const uint32_t* B1_ = stg + B1_OFF;
        const uint32_t* B3_ = stg + B3_OFF;

#pragma unroll
        for (int ks = 0; ks < 2; ks++) {
            int kk = ks * 8;                            // word offset of k16 substep
            uint32_t a[2][4];
#pragma unroll
            for (int mi = 0; mi < 2; mi++) {
                int mr = wm * 32 + mi * 16 + t8;
                a[mi][0] = A_[mr * 20 + kk + t4];
                a[mi][1] = A_[(mr + 8) * 20 + kk + t4];
                a[mi][2] = A_[mr * 20 + kk + t4 + 4];
                a[mi][3] = A_[(mr + 8) * 20 + kk + t4 + 4];
            }
            uint32_t b1r[4][2], b3r[4][2];
#pragma unroll
            for (int nj = 0; nj < 4; nj++) {
                int nc = wn * 32 + nj * 8 + t8;
                int w = nc * 20 + kk + t4;
                b1r[nj][0] = B1_[w];
                b1r[nj][1] = B1_[w + 4];
                b3r[nj][0] = B3_[w];
                b3r[nj][1] = B3_[w + 4];
            }
#pragma unroll
            for (int mi = 0; mi < 2; mi++)
#pragma unroll
                for (int nj = 0; nj < 4; nj++) {
                    mma16(accG[mi][nj], a[mi], b1r[nj]);
                    mma16(accU[mi][nj], a[mi], b3r[nj]);
                }
        }
    }

    // epilogue: silu(G)*U -> g_hidden (fp16)
#pragma unroll
    for (int mi = 0; mi < 2; mi++) {
#pragma unroll
        for (int h = 0; h < 2; h++) {
            int row = wm * 32 + mi * 16 + t8 + h * 8;
            int grow = bm0 + row;
            if (grow < M) {
                size_t base = (size_t)(rowbase + grow) * HH + n0;
#pragma unroll
                for (int nj = 0; nj < 4; nj++) {
                    int col = wn * 32 + nj * 8 + t4 * 2;
                    float v0 = silu_f(accG[mi][nj][h * 2 + 0]) * accU[mi][nj][h * 2 + 0];
                    float v1 = silu_f(accG[mi][nj][h * 2 + 1]) * accU[mi][nj][h * 2 + 1];
                    __half2 hh = __floats2half2_rn(v0, v1);
                    *reinterpret_cast<__half2*>(&g_hidden[base + col]) = hh;
                }
            }
        }
    }
}

// ---------------------------------------------------------------------------
// GEMM2 (fp16): y = hidden @ W2. CTA 128x128, warp 32x64, K32 stages.
// ---------------------------------------------------------------------------
#define B2_OFF   A_WORDS
#define B2_WORDS (128 * 20)                 // 2560
#define STG2_WORDS (A_WORDS + B2_WORDS)     // 5120 words = 20480 B
#define STG2_BYTES (STG2_WORDS * 4)
#define SMEM2_BYTES (4 * STG2_BYTES)        // 81920

__global__ __launch_bounds__(256, 2)
void gemm2_kernel(float* __restrict__ out) {
    extern __shared__ uint32_t smemw[];

    int g = blockIdx.z;
    int M, rowbase;
    const __half* W2H;
    if (g < EE) {
        M = g_count[g]; rowbase = g_offs[g];
        W2H = g_w2h + (size_t)g * HH * DD;
    } else {
        M = TT; rowbase = NMOE; W2H = g_sw2h;
    }
    int bm0 = blockIdx.x * 128;
    if (bm0 >= M) return;
    int n0 = blockIdx.y * 128;

    int tid  = threadIdx.x;
    int lane = tid & 31, wid = tid >> 5;
    int wm = wid & 3, wn = wid >> 2;       // warp 32 x 64
    int t4 = lane & 3, t8 = lane >> 2;

    float acc[2][8][4] = {};

    // producer: 1024 chunks (A 512, B 512) -> 4 per thread
    const __half* src[4];
    int sz[4], off[4];
#pragma unroll
    for (int j = 0; j < 4; j++) {
        int c = tid + 256 * j;
        if (c < 512) {
            int row = c >> 2, kw = (c & 3) << 2;
            int gm = bm0 + row;
            if (gm < M) {
                src[j] = g_hidden + (size_t)(rowbase + gm) * HH + kw * 2; sz[j] = 16;
            } else { src[j] = g_hidden; sz[j] = 0; }
            off[j] = A_OFF + row * 20 + kw;
        } else {
            int n = (c - 512) >> 2, kw = (c & 3) << 2;
            src[j] = W2H + (size_t)(n0 + n) * HH + kw * 2; sz[j] = 16;
            off[j] = B2_OFF + n * 20 + kw;
        }
    }

    uint32_t sbase = (uint32_t)__cvta_generic_to_shared(smemw);

#pragma unroll
    for (int p = 0; p < 2; p++) {
        uint32_t sb = sbase + p * STG2_BYTES;
        int k0 = p * 32;
#pragma unroll
        for (int j = 0; j < 4; j++) cp16(sb + off[j] * 4, src[j] + k0, sz[j]);
        cp_commit();
    }

    const int KB = HH / 32;                 // 64
    for (int kb = 0; kb < KB; kb++) {
        if (kb + 2 < KB) {
            uint32_t sb = sbase + ((kb + 2) & 3) * STG2_BYTES;
            int k0 = (kb + 2) * 32;
#pragma unroll
            for (int j = 0; j < 4; j++) cp16(sb + off[j] * 4, src[j] + k0, sz[j]);
        }
        cp_commit();
        cp_wait2();
        __syncthreads();

        const uint32_t* stg = smemw + (kb & 3) * STG2_WORDS;
        const uint32_t* A_ = stg + A_OFF;
        const uint32_t* B_ = stg + B2_OFF;

#pragma unroll
        for (int ks = 0; ks < 2; ks++) {
            int kk = ks * 8;
            uint32_t a[2][4];
#pragma unroll
            for (int mi = 0; mi < 2; mi++) {
                int mr = wm * 32 + mi * 16 + t8;
                a[mi][0] = A_[mr * 20 + kk + t4];
                a[mi][1] = A_[(mr + 8) * 20 + kk + t4];
                a[mi][2] = A_[mr * 20 + kk + t4 + 4];
                a[mi][3] = A_[(mr + 8) * 20 + kk + t4 + 4];
            }
            uint32_t br[8][2];
#pragma unroll
            for (int nj = 0; nj < 8; nj++) {
                int nc = wn * 64 + nj * 8 + t8;
                int w = nc * 20 + kk + t4;
                br[nj][0] = B_[w];
                br[nj][1] = B_[w + 4];
            }
#pragma unroll
            for (int mi = 0; mi < 2; mi++)
#pragma unroll
                for (int nj = 0; nj < 8; nj++)
                    mma16(acc[mi][nj], a[mi], br[nj]);
        }
    }

#pragma unroll
    for (int mi = 0; mi < 2; mi++) {
#pragma unroll
        for (int h = 0; h < 2; h++) {
            int row = wm * 32 + mi * 16 + t8 + h * 8;
            int grow = bm0 + row;
            if (grow < M) {
#pragma unroll
                for (int nj = 0; nj < 8; nj++) {
                    int col = wn * 64 + nj * 8 + t4 * 2;
                    float2 st;
                    st.x = acc[mi][nj][h * 2 + 0];
                    st.y = acc[mi][nj][h * 2 + 1];
                    if (g < EE) {
                        size_t base = (size_t)(rowbase + grow) * DD + n0;
                        *reinterpret_cast<float2*>(&g_y[base + col]) = st;
                    } else {
                        size_t base = (size_t)grow * DD + n0;   // grow == token id
                        *reinterpret_cast<float2*>(&out[base + col]) = st;
                    }
                }
            }
        }
    }
}

// ---------------------------------------------------------------------------
// K5: combine
// ---------------------------------------------------------------------------
__global__ void combine_kernel(float* __restrict__ out) {
    int t = blockIdx.x;
    int e0 = g_asg_e[2 * t],     e1 = g_asg_e[2 * t + 1];
    int r0 = g_offs[e0] + g_asg_pos[2 * t];
    int r1 = g_offs[e1] + g_asg_pos[2 * t + 1];
    float w0 = g_asg_w[2 * t], w1 = g_asg_w[2 * t + 1];

    int c = threadIdx.x * 4;
    float4 o  = *reinterpret_cast<const float4*>(out + (size_t)t * DD + c);
    float4 y0 = *reinterpret_cast<const float4*>(g_y + (size_t)r0 * DD + c);
    float4 y1 = *reinterpret_cast<const float4*>(g_y + (size_t)r1 * DD + c);
    o.x += w0 * y0.x + w1 * y1.x;
    o.y += w0 * y0.y + w1 * y1.y;
    o.z += w0 * y0.z + w1 * y1.z;
    o.w += w0 * y0.w + w1 * y1.w;
    *reinterpret_cast<float4*>(out + (size_t)t * DD + c) = o;
}

// ---------------------------------------------------------------------------
// Launch
// ---------------------------------------------------------------------------
extern "C" void kernel_launch(void* const* d_in, const int* in_sizes, int n_in,
                              void* d_out, int out_size) {
    const float* x    = (const float*)d_in[0];
    const float* rw   = (const float*)d_in[1];
    const float* bias = (const float*)d_in[2];
    const float* w1   = (const float*)d_in[3];
    const float* w3   = (const float*)d_in[4];
    const float* w2   = (const float*)d_in[5];
    const float* sw1  = (const float*)d_in[6];
    const float* sw3  = (const float*)d_in[7];
    const float* sw2  = (const float*)d_in[8];
    float* out = (float*)d_out;

    cudaFuncSetAttribute(gemm1_kernel, cudaFuncAttributeMaxDynamicSharedMemorySize, SMEM1_BYTES);
    cudaFuncSetAttribute(gemm2_kernel, cudaFuncAttributeMaxDynamicSharedMemorySize, SMEM2_BYTES);

    __half* xh;   cudaGetSymbolAddress((void**)&xh,  g_xh);
    __half* w1h;  cudaGetSymbolAddress((void**)&w1h, g_w1h);
    __half* w3h;  cudaGetSymbolAddress((void**)&w3h, g_w3h);
    __half* w2h;  cudaGetSymbolAddress((void**)&w2h, g_w2h);
    __half* s1h;  cudaGetSymbolAddress((void**)&s1h, g_sw1h);
    __half* s3h;  cudaGetSymbolAddress((void**)&s3h, g_sw3h);
    __half* s2h;  cudaGetSymbolAddress((void**)&s2h, g_sw2h);

    // x: fp16 convert, row-major (A side)
    cvt_f16_kernel<<<1792, 256>>>((const float4*)x, (uint2*)xh, (int)(XSZ / 4));

    // weights: transpose + fp16 convert to [N][K]
    {
        dim3 gw(HH / 32, DD / 32, EE);
        trans_cvt_h<<<gw, 256>>>(w1, w1h, DD, HH);
        trans_cvt_h<<<gw, 256>>>(w3, w3h, DD, HH);
        dim3 gs(HH / 32, DD / 32, 1);
        trans_cvt_h<<<gs, 256>>>(sw1, s1h, DD, HH);
        trans_cvt_h<<<gs, 256>>>(sw3, s3h, DD, HH);
    }
    {
        dim3 gw(DD / 32, HH / 32, EE);
        trans_cvt_h<<<gw, 256>>>(w2, w2h, HH, DD);
        dim3 gs(DD / 32, HH / 32, 1);
        trans_cvt_h<<<gs, 256>>>(sw2, s2h, HH, DD);
    }

    zero_counts_kernel<<<1, 32>>>();
    router_kernel<<<TT / 8, 256>>>(x, rw, bias);
    offsets_kernel<<<1, 32>>>();

    dim3 grid1(TT / 128, HH / 64, EE + 1);       // (64, 32, 9)
    gemm1_kernel<<<grid1, 256, SMEM1_BYTES>>>();

    dim3 grid2(TT / 128, DD / 128, EE + 1);      // (64, 8, 9)
    gemm2_kernel<<<grid2, 256, SMEM2_BYTES>>>(out);

    combine_kernel<<<TT, 256>>>(out);
}

// round 14
// speedup vs baseline: 1.9883x; 1.1440x over previous
#include <cuda_runtime.h>
#include <cuda_fp16.h>
#include <math.h>
#include <stdint.h>

// Problem constants
#define DD   1024
#define HH   2048
#define EE   8
#define TT   8192
#define KTOP 2
#define NMOE (TT * KTOP)
#define NROWS (NMOE + TT)

#define XSZ   ((size_t)TT * DD)
#define WSZ   ((size_t)EE * DD * HH)
#define SWSZ  ((size_t)DD * HH)

// ---------------------------------------------------------------------------
// Scratch (static __device__ globals)
// ---------------------------------------------------------------------------
__device__ __half g_hidden[(size_t)NROWS * HH];   // fp16 activations
__device__ float  g_y[(size_t)NMOE * DD];
__device__ __half g_xh[XSZ];                      // x fp16, [T][D]
__device__ __half g_w1h[WSZ];                     // W1^T fp16: [E][H][D]
__device__ __half g_w3h[WSZ];
__device__ __half g_w2h[WSZ];                     // W2^T fp16: [E][D][H]
__device__ __half g_sw1h[SWSZ];
__device__ __half g_sw3h[SWSZ];
__device__ __half g_sw2h[SWSZ];
__device__ int   g_count[EE];
__device__ int   g_offs[EE + 1];
__device__ int   g_tok[EE * TT];
__device__ int   g_asg_e[NMOE];
__device__ int   g_asg_pos[NMOE];
__device__ float g_asg_w[NMOE];

// ---------------------------------------------------------------------------
// Helpers
// ---------------------------------------------------------------------------
__device__ __forceinline__ void mma16(float c[4], const uint32_t a[4], const uint32_t* b) {
    asm volatile(
        "mma.sync.aligned.m16n8k16.row.col.f32.f16.f16.f32 "
        "{%0,%1,%2,%3},{%4,%5,%6,%7},{%8,%9},{%0,%1,%2,%3};\n"
        : "+f"(c[0]), "+f"(c[1]), "+f"(c[2]), "+f"(c[3])
        : "r"(a[0]), "r"(a[1]), "r"(a[2]), "r"(a[3]), "r"(b[0]), "r"(b[1]));
}

__device__ __forceinline__ void ldsm4(uint32_t r[4], uint32_t addr) {
    asm volatile("ldmatrix.sync.aligned.m8n8.x4.shared.b16 {%0,%1,%2,%3}, [%4];"
                 : "=r"(r[0]), "=r"(r[1]), "=r"(r[2]), "=r"(r[3]) : "r"(addr));
}

__device__ __forceinline__ void cp16(uint32_t smem_dst, const void* gmem_src, int src_size) {
    asm volatile("cp.async.ca.shared.global [%0], [%1], 16, %2;"
                 :: "r"(smem_dst), "l"(gmem_src), "r"(src_size));
}
__device__ __forceinline__ void cp_commit() { asm volatile("cp.async.commit_group;"); }
__device__ __forceinline__ void cp_wait2()  { asm volatile("cp.async.wait_group 2;" ::: "memory"); }

__device__ __forceinline__ float silu_f(float v) { return v / (1.0f + __expf(-v)); }

// ---------------------------------------------------------------------------
// Prep: x fp32 -> fp16 (vectorized)
// ---------------------------------------------------------------------------
__global__ void cvt_f16_kernel(const float4* __restrict__ src, uint2* __restrict__ dst, int n4) {
    int i = blockIdx.x * blockDim.x + threadIdx.x;
    int stride = gridDim.x * blockDim.x;
    for (; i < n4; i += stride) {
        float4 v = src[i];
        __half2 h0 = __floats2half2_rn(v.x, v.y);
        __half2 h1 = __floats2half2_rn(v.z, v.w);
        uint2 o;
        o.x = *reinterpret_cast<uint32_t*>(&h0);
        o.y = *reinterpret_cast<uint32_t*>(&h1);
        dst[i] = o;
    }
}

// Prep: batched transpose+convert for the [D][H] family (w1, w3, sw1, sw3)
// z < EE: w1 expert z; z < 2EE: w3; z == 2EE: sw1; z == 2EE+1: sw3
__global__ void trans_cvt_f1(const float* __restrict__ w1, const float* __restrict__ w3,
                             const float* __restrict__ sw1, const float* __restrict__ sw3,
                             __half* __restrict__ d1, __half* __restrict__ d3,
                             __half* __restrict__ ds1, __half* __restrict__ ds3) {
    const int K = DD, N = HH;
    int z = blockIdx.z;
    const float* src;
    __half* dst;
    if (z < EE)            { src = w1  + (size_t)z * K * N;        dst = d1  + (size_t)z * K * N; }
    else if (z < 2 * EE)   { src = w3  + (size_t)(z - EE) * K * N; dst = d3  + (size_t)(z - EE) * K * N; }
    else if (z == 2 * EE)  { src = sw1;                            dst = ds1; }
    else                   { src = sw3;                            dst = ds3; }

    __shared__ float t[32][33];
    int n0 = blockIdx.x * 32, k0 = blockIdx.y * 32;
    int tx = threadIdx.x & 31, ty = threadIdx.x >> 5;
#pragma unroll
    for (int i = 0; i < 4; i++)
        t[ty + 8 * i][tx] = src[(size_t)(k0 + ty + 8 * i) * N + n0 + tx];
    __syncthreads();
#pragma unroll
    for (int i = 0; i < 4; i++)
        dst[(size_t)(n0 + ty + 8 * i) * K + k0 + tx] = __float2half_rn(t[tx][ty + 8 * i]);
}

// [H][D] family (w2, sw2): z < EE: w2 expert z; z == EE: sw2
__global__ void trans_cvt_f2(const float* __restrict__ w2, const float* __restrict__ sw2,
                             __half* __restrict__ d2, __half* __restrict__ ds2) {
    const int K = HH, N = DD;
    int z = blockIdx.z;
    const float* src = (z < EE) ? (w2 + (size_t)z * K * N) : sw2;
    __half* dst      = (z < EE) ? (d2 + (size_t)z * K * N) : ds2;

    __shared__ float t[32][33];
    int n0 = blockIdx.x * 32, k0 = blockIdx.y * 32;
    int tx = threadIdx.x & 31, ty = threadIdx.x >> 5;
#pragma unroll
    for (int i = 0; i < 4; i++)
        t[ty + 8 * i][tx] = src[(size_t)(k0 + ty + 8 * i) * N + n0 + tx];
    __syncthreads();
#pragma unroll
    for (int i = 0; i < 4; i++)
        dst[(size_t)(n0 + ty + 8 * i) * K + k0 + tx] = __float2half_rn(t[tx][ty + 8 * i]);
}

// ---------------------------------------------------------------------------
// Routing kernels
// ---------------------------------------------------------------------------
__global__ void zero_counts_kernel() {
    if (threadIdx.x < EE) g_count[threadIdx.x] = 0;
}

__global__ void router_kernel(const float* __restrict__ x, const float* __restrict__ rw,
                              const float* __restrict__ bias) {
    int warp = threadIdx.x >> 5;
    int lane = threadIdx.x & 31;
    int t = blockIdx.x * 8 + warp;

    const float* xr = x + (size_t)t * DD;
    float xv[32];
#pragma unroll
    for (int i = 0; i < 32; i++) xv[i] = xr[lane + (i << 5)];

    float logit[EE];
#pragma unroll
    for (int e = 0; e < EE; e++) {
        const float* we = rw + e * DD;
        float acc = 0.0f;
#pragma unroll
        for (int i = 0; i < 32; i++) acc += xv[i] * we[lane + (i << 5)];
#pragma unroll
        for (int o = 16; o > 0; o >>= 1) acc += __shfl_xor_sync(0xffffffffu, acc, o);
        logit[e] = acc + bias[e];
    }

    if (lane == 0) {
        int e0 = 0;
#pragma unroll
        for (int e = 1; e < EE; e++) if (logit[e] > logit[e0]) e0 = e;
        int e1 = -1;
#pragma unroll
        for (int e = 0; e < EE; e++) {
            if (e == e0) continue;
            if (e1 < 0 || logit[e] > logit[e1]) e1 = e;
        }
        float l0 = logit[e0], l1 = logit[e1];
        float p1 = expf(l1 - l0);
        float inv = 1.0f / (1.0f + p1);
        float w0 = inv, w1 = p1 * inv;

        int pos0 = atomicAdd(&g_count[e0], 1);
        int pos1 = atomicAdd(&g_count[e1], 1);
        g_tok[e0 * TT + pos0] = t;
        g_tok[e1 * TT + pos1] = t;
        g_asg_e[2 * t]     = e0; g_asg_pos[2 * t]     = pos0; g_asg_w[2 * t]     = w0;
        g_asg_e[2 * t + 1] = e1; g_asg_pos[2 * t + 1] = pos1; g_asg_w[2 * t + 1] = w1;
    }
}

__global__ void offsets_kernel() {
    if (threadIdx.x == 0 && blockIdx.x == 0) {
        int a = 0;
        for (int e = 0; e < EE; e++) { g_offs[e] = a; a += g_count[e]; }
        g_offs[EE] = a;
    }
}

// ---------------------------------------------------------------------------
// GEMM1 (dual fp16): hidden = silu(X W1) * (X W3). CTA 128x64(dual), K32 stages,
// ldmatrix.x4 fragment loads, 4-stage cp.async ring (R13 structure).
// ---------------------------------------------------------------------------
#define A_OFF    0
#define A_WORDS  (128 * 20)
#define B1_OFF   A_WORDS
#define B1_WORDS (64 * 20)
#define B3_OFF   (B1_OFF + B1_WORDS)
#define STG1_WORDS (A_WORDS + 2 * B1_WORDS)
#define STG1_BYTES (STG1_WORDS * 4)
#define SMEM1_BYTES (4 * STG1_BYTES)        // 81920

__global__ __launch_bounds__(256, 2)
void gemm1_kernel() {
    extern __shared__ uint32_t smemw[];

    int g = blockIdx.z;
    int M, rowbase;
    const int* toks;
    const __half *W1H, *W3H;
    if (g < EE) {
        M = g_count[g]; rowbase = g_offs[g]; toks = g_tok + g * TT;
        W1H = g_w1h + (size_t)g * DD * HH; W3H = g_w3h + (size_t)g * DD * HH;
    } else {
        M = TT; rowbase = NMOE; toks = nullptr;
        W1H = g_sw1h; W3H = g_sw3h;
    }
    int bm0 = blockIdx.x * 128;
    if (bm0 >= M) return;
    int n0 = blockIdx.y * 64;

    int tid  = threadIdx.x;
    int lane = tid & 31, wid = tid >> 5;
    int wm = wid & 3, wn = wid >> 2;       // 4x2 warps -> 32x32 per warp (dual)
    int t4 = lane & 3, t8 = lane >> 2;

    float accG[2][4][4] = {}, accU[2][4][4] = {};

    // producer: 1024 chunks (A 512, B1 256, B3 256) -> 4 per thread
    const __half* src[4];
    int sz[4], off[4];
#pragma unroll
    for (int j = 0; j < 4; j++) {
        int c = tid + 256 * j;
        if (c < 512) {
            int row = c >> 2, kw = (c & 3) << 2;
            int gm = bm0 + row;
            if (gm < M) {
                int tr = toks ? toks[gm] : gm;
                src[j] = g_xh + (size_t)tr * DD + kw * 2; sz[j] = 16;
            } else { src[j] = g_xh; sz[j] = 0; }
            off[j] = A_OFF + row * 20 + kw;
        } else if (c < 768) {
            int n = (c - 512) >> 2, kw = (c & 3) << 2;
            src[j] = W1H + (size_t)(n0 + n) * DD + kw * 2; sz[j] = 16;
            off[j] = B1_OFF + n * 20 + kw;
        } else {
            int n = (c - 768) >> 2, kw = (c & 3) << 2;
            src[j] = W3H + (size_t)(n0 + n) * DD + kw * 2; sz[j] = 16;
            off[j] = B3_OFF + n * 20 + kw;
        }
    }

    uint32_t sbase = (uint32_t)__cvta_generic_to_shared(smemw);

    // ldmatrix per-lane word offsets (within a stage)
    // A x4: lanes 0-15 rows m..m+15 kgroup0; lanes 16-31 same rows kgroup1
    int awo[2];
#pragma unroll
    for (int mi = 0; mi < 2; mi++)
        awo[mi] = A_OFF + (wm * 32 + mi * 16 + (lane & 15)) * 20 + ((lane >> 4) << 2);
    // B x4 (nj pair p): lanes 0-7 rows kg0, 8-15 rows kg1, 16-23 rows+8 kg0, 24-31 rows+8 kg1
    int bwo1[2], bwo3[2];
#pragma unroll
    for (int p = 0; p < 2; p++) {
        int rowoff = (wn * 32 + p * 16 + ((lane >> 4) << 3) + (lane & 7)) * 20
                   + (((lane >> 3) & 1) << 2);
        bwo1[p] = B1_OFF + rowoff;
        bwo3[p] = B3_OFF + rowoff;
    }

    // prologue: prefetch stages 0, 1
#pragma unroll
    for (int p = 0; p < 2; p++) {
        uint32_t sb = sbase + p * STG1_BYTES;
        int k0 = p * 32;
#pragma unroll
        for (int j = 0; j < 4; j++) cp16(sb + off[j] * 4, src[j] + k0, sz[j]);
        cp_commit();
    }

    const int KB = DD / 32;
    for (int kb = 0; kb < KB; kb++) {
        if (kb + 2 < KB) {
            uint32_t sb = sbase + ((kb + 2) & 3) * STG1_BYTES;
            int k0 = (kb + 2) * 32;
#pragma unroll
            for (int j = 0; j < 4; j++) cp16(sb + off[j] * 4, src[j] + k0, sz[j]);
        }
        cp_commit();
        cp_wait2();
        __syncthreads();

        uint32_t stgb = sbase + (kb & 3) * STG1_BYTES;

#pragma unroll
        for (int ks = 0; ks < 2; ks++) {
            uint32_t kofs = stgb + ks * 32;            // ks*8 words = 32 bytes
            uint32_t a[2][4], b1[2][4], b3[2][4];
            ldsm4(a[0],  kofs + awo[0] * 4);
            ldsm4(a[1],  kofs + awo[1] * 4);
            ldsm4(b1[0], kofs + bwo1[0] * 4);
            ldsm4(b1[1], kofs + bwo1[1] * 4);
            ldsm4(b3[0], kofs + bwo3[0] * 4);
            ldsm4(b3[1], kofs + bwo3[1] * 4);
#pragma unroll
            for (int mi = 0; mi < 2; mi++)
#pragma unroll
                for (int nj = 0; nj < 4; nj++) {
                    mma16(accG[mi][nj], a[mi], &b1[nj >> 1][(nj & 1) * 2]);
                    mma16(accU[mi][nj], a[mi], &b3[nj >> 1][(nj & 1) * 2]);
                }
        }
    }

    // epilogue: silu(G)*U -> g_hidden (fp16)
#pragma unroll
    for (int mi = 0; mi < 2; mi++) {
#pragma unroll
        for (int h = 0; h < 2; h++) {
            int row = wm * 32 + mi * 16 + t8 + h * 8;
            int grow = bm0 + row;
            if (grow < M) {
                size_t base = (size_t)(rowbase + grow) * HH + n0;
#pragma unroll
                for (int nj = 0; nj < 4; nj++) {
                    int col = wn * 32 + nj * 8 + t4 * 2;
                    float v0 = silu_f(accG[mi][nj][h * 2 + 0]) * accU[mi][nj][h * 2 + 0];
                    float v1 = silu_f(accG[mi][nj][h * 2 + 1]) * accU[mi][nj][h * 2 + 1];
                    __half2 hh = __floats2half2_rn(v0, v1);
                    *reinterpret_cast<__half2*>(&g_hidden[base + col]) = hh;
                }
            }
        }
    }
}

// ---------------------------------------------------------------------------
// GEMM2 (fp16): y = hidden @ W2. CTA 128x128, warp 32x64, K32 stages, ldmatrix.
// ---------------------------------------------------------------------------
#define B2_OFF   A_WORDS
#define B2_WORDS (128 * 20)
#define STG2_WORDS (A_WORDS + B2_WORDS)
#define STG2_BYTES (STG2_WORDS * 4)
#define SMEM2_BYTES (4 * STG2_BYTES)        // 81920

__global__ __launch_bounds__(256, 2)
void gemm2_kernel(float* __restrict__ out) {
    extern __shared__ uint32_t smemw[];

    int g = blockIdx.z;
    int M, rowbase;
    const __half* W2H;
    if (g < EE) {
        M = g_count[g]; rowbase = g_offs[g];
        W2H = g_w2h + (size_t)g * HH * DD;
    } else {
        M = TT; rowbase = NMOE; W2H = g_sw2h;
    }
    int bm0 = blockIdx.x * 128;
    if (bm0 >= M) return;
    int n0 = blockIdx.y * 128;

    int tid  = threadIdx.x;
    int lane = tid & 31, wid = tid >> 5;
    int wm = wid & 3, wn = wid >> 2;       // warp 32 x 64
    int t4 = lane & 3, t8 = lane >> 2;

    float acc[2][8][4] = {};

    const __half* src[4];
    int sz[4], off[4];
#pragma unroll
    for (int j = 0; j < 4; j++) {
        int c = tid + 256 * j;
        if (c < 512) {
            int row = c >> 2, kw = (c & 3) << 2;
            int gm = bm0 + row;
            if (gm < M) {
                src[j] = g_hidden + (size_t)(rowbase + gm) * HH + kw * 2; sz[j] = 16;
            } else { src[j] = g_hidden; sz[j] = 0; }
            off[j] = A_OFF + row * 20 + kw;
        } else {
            int n = (c - 512) >> 2, kw = (c & 3) << 2;
            src[j] = W2H + (size_t)(n0 + n) * HH + kw * 2; sz[j] = 16;
            off[j] = B2_OFF + n * 20 + kw;
        }
    }

    uint32_t sbase = (uint32_t)__cvta_generic_to_shared(smemw);

    int awo[2];
#pragma unroll
    for (int mi = 0; mi < 2; mi++)
        awo[mi] = A_OFF + (wm * 32 + mi * 16 + (lane & 15)) * 20 + ((lane >> 4) << 2);
    int bwo[4];
#pragma unroll
    for (int p = 0; p < 4; p++) {
        bwo[p] = B2_OFF + (wn * 64 + p * 16 + ((lane >> 4) << 3) + (lane & 7)) * 20
               + (((lane >> 3) & 1) << 2);
    }

#pragma unroll
    for (int p = 0; p < 2; p++) {
        uint32_t sb = sbase + p * STG2_BYTES;
        int k0 = p * 32;
#pragma unroll
        for (int j = 0; j < 4; j++) cp16(sb + off[j] * 4, src[j] + k0, sz[j]);
        cp_commit();
    }

    const int KB = HH / 32;
    for (int kb = 0; kb < KB; kb++) {
        if (kb + 2 < KB) {
            uint32_t sb = sbase + ((kb + 2) & 3) * STG2_BYTES;
            int k0 = (kb + 2) * 32;
#pragma unroll
            for (int j = 0; j < 4; j++) cp16(sb + off[j] * 4, src[j] + k0, sz[j]);
        }
        cp_commit();
        cp_wait2();
        __syncthreads();

        uint32_t stgb = sbase + (kb & 3) * STG2_BYTES;

#pragma unroll
        for (int ks = 0; ks < 2; ks++) {
            uint32_t kofs = stgb + ks * 32;
            uint32_t a[2][4], bb[4][4];
            ldsm4(a[0], kofs + awo[0] * 4);
            ldsm4(a[1], kofs + awo[1] * 4);
#pragma unroll
            for (int p = 0; p < 4; p++) ldsm4(bb[p], kofs + bwo[p] * 4);
#pragma unroll
            for (int mi = 0; mi < 2; mi++)
#pragma unroll
                for (int nj = 0; nj < 8; nj++)
                    mma16(acc[mi][nj], a[mi], &bb[nj >> 1][(nj & 1) * 2]);
        }
    }

#pragma unroll
    for (int mi = 0; mi < 2; mi++) {
#pragma unroll
        for (int h = 0; h < 2; h++) {
            int row = wm * 32 + mi * 16 + t8 + h * 8;
            int grow = bm0 + row;
            if (grow < M) {
#pragma unroll
                for (int nj = 0; nj < 8; nj++) {
                    int col = wn * 64 + nj * 8 + t4 * 2;
                    float2 st;
                    st.x = acc[mi][nj][h * 2 + 0];
                    st.y = acc[mi][nj][h * 2 + 1];
                    if (g < EE) {
                        size_t base = (size_t)(rowbase + grow) * DD + n0;
                        *reinterpret_cast<float2*>(&g_y[base + col]) = st;
                    } else {
                        size_t base = (size_t)grow * DD + n0;   // grow == token id
                        *reinterpret_cast<float2*>(&out[base + col]) = st;
                    }
                }
            }
        }
    }
}

// ---------------------------------------------------------------------------
// K5: combine
// ---------------------------------------------------------------------------
__global__ void combine_kernel(float* __restrict__ out) {
    int t = blockIdx.x;
    int e0 = g_asg_e[2 * t],     e1 = g_asg_e[2 * t + 1];
    int r0 = g_offs[e0] + g_asg_pos[2 * t];
    int r1 = g_offs[e1] + g_asg_pos[2 * t + 1];
    float w0 = g_asg_w[2 * t], w1 = g_asg_w[2 * t + 1];

    int c = threadIdx.x * 4;
    float4 o  = *reinterpret_cast<const float4*>(out + (size_t)t * DD + c);
    float4 y0 = *reinterpret_cast<const float4*>(g_y + (size_t)r0 * DD + c);
    float4 y1 = *reinterpret_cast<const float4*>(g_y + (size_t)r1 * DD + c);
    o.x += w0 * y0.x + w1 * y1.x;
    o.y += w0 * y0.y + w1 * y1.y;
    o.z += w0 * y0.z + w1 * y1.z;
    o.w += w0 * y0.w + w1 * y1.w;
    *reinterpret_cast<float4*>(out + (size_t)t * DD + c) = o;
}

// ---------------------------------------------------------------------------
// Launch
// ---------------------------------------------------------------------------
extern "C" void kernel_launch(void* const* d_in, const int* in_sizes, int n_in,
                              void* d_out, int out_size) {
    const float* x    = (const float*)d_in[0];
    const float* rw   = (const float*)d_in[1];
    const float* bias = (const float*)d_in[2];
    const float* w1   = (const float*)d_in[3];
    const float* w3   = (const float*)d_in[4];
    const float* w2   = (const float*)d_in[5];
    const float* sw1  = (const float*)d_in[6];
    const float* sw3  = (const float*)d_in[7];
    const float* sw2  = (const float*)d_in[8];
    float* out = (float*)d_out;

    cudaFuncSetAttribute(gemm1_kernel, cudaFuncAttributeMaxDynamicSharedMemorySize, SMEM1_BYTES);
    cudaFuncSetAttribute(gemm2_kernel, cudaFuncAttributeMaxDynamicSharedMemorySize, SMEM2_BYTES);

    __half* xh;   cudaGetSymbolAddress((void**)&xh,  g_xh);
    __half* w1h;  cudaGetSymbolAddress((void**)&w1h, g_w1h);
    __half* w3h;  cudaGetSymbolAddress((void**)&w3h, g_w3h);
    __half* w2h;  cudaGetSymbolAddress((void**)&w2h, g_w2h);
    __half* s1h;  cudaGetSymbolAddress((void**)&s1h, g_sw1h);
    __half* s3h;  cudaGetSymbolAddress((void**)&s3h, g_sw3h);
    __half* s2h;  cudaGetSymbolAddress((void**)&s2h, g_sw2h);

    // x: fp16 convert, row-major
    cvt_f16_kernel<<<1792, 256>>>((const float4*)x, (uint2*)xh, (int)(XSZ / 4));

    // weights: batched transpose + fp16 convert
    {
        dim3 g1(HH / 32, DD / 32, 2 * EE + 2);
        trans_cvt_f1<<<g1, 256>>>(w1, w3, sw1, sw3, w1h, w3h, s1h, s3h);
        dim3 g2(DD / 32, HH / 32, EE + 1);
        trans_cvt_f2<<<g2, 256>>>(w2, sw2, w2h, s2h);
    }

    zero_counts_kernel<<<1, 32>>>();
    router_kernel<<<TT / 8, 256>>>(x, rw, bias);
    offsets_kernel<<<1, 32>>>();

    dim3 grid1(TT / 128, HH / 64, EE + 1);       // (64, 32, 9)
    gemm1_kernel<<<grid1, 256, SMEM1_BYTES>>>();

    dim3 grid2(TT / 128, DD / 128, EE + 1);      // (64, 8, 9)
    gemm2_kernel<<<grid2, 256, SMEM2_BYTES>>>(out);

    combine_kernel<<<TT, 256>>>(out);
}

// round 15
// speedup vs baseline: 2.0269x; 1.0194x over previous
#include <cuda_runtime.h>
#include <cuda_fp16.h>
#include <math.h>
#include <stdint.h>

// Problem constants
#define DD   1024
#define HH   2048
#define EE   8
#define TT   8192
#define KTOP 2
#define NMOE (TT * KTOP)
#define NROWS (NMOE + TT)

#define XSZ   ((size_t)TT * DD)
#define WSZ   ((size_t)EE * DD * HH)
#define SWSZ  ((size_t)DD * HH)

// ---------------------------------------------------------------------------
// Scratch (static __device__ globals)
// ---------------------------------------------------------------------------
__device__ __half g_hidden[(size_t)NROWS * HH];   // fp16 activations
__device__ __half g_xh[XSZ];                      // x fp16, [T][D] (written by router)
__device__ __half g_w1h[WSZ];                     // W1^T fp16: [E][H][D]
__device__ __half g_w3h[WSZ];
__device__ __half g_w2h[WSZ];                     // W2^T fp16: [E][D][H]
__device__ __half g_sw1h[SWSZ];
__device__ __half g_sw3h[SWSZ];
__device__ __half g_sw2h[SWSZ];
__device__ int   g_count[EE];
__device__ int   g_offs[EE + 1];
__device__ int   g_tok[EE * TT];                  // per-expert token lists
__device__ float g_wt[EE * TT];                   // per-expert combine weights (by pos)

// ---------------------------------------------------------------------------
// Helpers
// ---------------------------------------------------------------------------
__device__ __forceinline__ void mma16(float c[4], const uint32_t a[4], const uint32_t* b) {
    asm volatile(
        "mma.sync.aligned.m16n8k16.row.col.f32.f16.f16.f32 "
        "{%0,%1,%2,%3},{%4,%5,%6,%7},{%8,%9},{%0,%1,%2,%3};\n"
        : "+f"(c[0]), "+f"(c[1]), "+f"(c[2]), "+f"(c[3])
        : "r"(a[0]), "r"(a[1]), "r"(a[2]), "r"(a[3]), "r"(b[0]), "r"(b[1]));
}

__device__ __forceinline__ void ldsm4(uint32_t r[4], uint32_t addr) {
    asm volatile("ldmatrix.sync.aligned.m8n8.x4.shared.b16 {%0,%1,%2,%3}, [%4];"
                 : "=r"(r[0]), "=r"(r[1]), "=r"(r[2]), "=r"(r[3]) : "r"(addr));
}

__device__ __forceinline__ void cp16(uint32_t smem_dst, const void* gmem_src, int src_size) {
    asm volatile("cp.async.ca.shared.global [%0], [%1], 16, %2;"
                 :: "r"(smem_dst), "l"(gmem_src), "r"(src_size));
}
__device__ __forceinline__ void cp_commit() { asm volatile("cp.async.commit_group;"); }
__device__ __forceinline__ void cp_wait2()  { asm volatile("cp.async.wait_group 2;" ::: "memory"); }

__device__ __forceinline__ void red2(float* ptr, float v0, float v1) {
    asm volatile("red.global.add.v2.f32 [%0], {%1, %2};"
                 :: "l"(ptr), "f"(v0), "f"(v1) : "memory");
}

__device__ __forceinline__ float silu_f(float v) { return v / (1.0f + __expf(-v)); }

// ---------------------------------------------------------------------------
// Prep: batched transpose+convert for the [D][H] family (w1, w3, sw1, sw3)
// ---------------------------------------------------------------------------
__global__ void trans_cvt_f1(const float* __restrict__ w1, const float* __restrict__ w3,
                             const float* __restrict__ sw1, const float* __restrict__ sw3,
                             __half* __restrict__ d1, __half* __restrict__ d3,
                             __half* __restrict__ ds1, __half* __restrict__ ds3) {
    const int K = DD, N = HH;
    int z = blockIdx.z;
    const float* src;
    __half* dst;
    if (z < EE)            { src = w1  + (size_t)z * K * N;        dst = d1  + (size_t)z * K * N; }
    else if (z < 2 * EE)   { src = w3  + (size_t)(z - EE) * K * N; dst = d3  + (size_t)(z - EE) * K * N; }
    else if (z == 2 * EE)  { src = sw1;                            dst = ds1; }
    else                   { src = sw3;                            dst = ds3; }

    __shared__ float t[32][33];
    int n0 = blockIdx.x * 32, k0 = blockIdx.y * 32;
    int tx = threadIdx.x & 31, ty = threadIdx.x >> 5;
#pragma unroll
    for (int i = 0; i < 4; i++)
        t[ty + 8 * i][tx] = src[(size_t)(k0 + ty + 8 * i) * N + n0 + tx];
    __syncthreads();
#pragma unroll
    for (int i = 0; i < 4; i++)
        dst[(size_t)(n0 + ty + 8 * i) * K + k0 + tx] = __float2half_rn(t[tx][ty + 8 * i]);
}

// [H][D] family (w2, sw2)
__global__ void trans_cvt_f2(const float* __restrict__ w2, const float* __restrict__ sw2,
                             __half* __restrict__ d2, __half* __restrict__ ds2) {
    const int K = HH, N = DD;
    int z = blockIdx.z;
    const float* src = (z < EE) ? (w2 + (size_t)z * K * N) : sw2;
    __half* dst      = (z < EE) ? (d2 + (size_t)z * K * N) : ds2;

    __shared__ float t[32][33];
    int n0 = blockIdx.x * 32, k0 = blockIdx.y * 32;
    int tx = threadIdx.x & 31, ty = threadIdx.x >> 5;
#pragma unroll
    for (int i = 0; i < 4; i++)
        t[ty + 8 * i][tx] = src[(size_t)(k0 + ty + 8 * i) * N + n0 + tx];
    __syncthreads();
#pragma unroll
    for (int i = 0; i < 4; i++)
        dst[(size_t)(n0 + ty + 8 * i) * K + k0 + tx] = __float2half_rn(t[tx][ty + 8 * i]);
}

// ---------------------------------------------------------------------------
// zero kernels
// ---------------------------------------------------------------------------
__global__ void zero_counts_kernel() {
    if (threadIdx.x < EE) g_count[threadIdx.x] = 0;
}
__global__ void zero_out_kernel(float4* __restrict__ out) {
    int i = blockIdx.x * blockDim.x + threadIdx.x;
    out[i] = make_float4(0.f, 0.f, 0.f, 0.f);
}

// ---------------------------------------------------------------------------
// Router: logits + top-2 + token lists; also emits x in fp16 (fused convert).
// One warp per token, float4 loads.
// ---------------------------------------------------------------------------
__global__ void router_kernel(const float* __restrict__ x, const float* __restrict__ rw,
                              const float* __restrict__ bias) {
    int warp = threadIdx.x >> 5;
    int lane = threadIdx.x & 31;
    int t = blockIdx.x * 8 + warp;

    const float4* xr4 = reinterpret_cast<const float4*>(x + (size_t)t * DD);
    float4 xv[8];
#pragma unroll
    for (int i = 0; i < 8; i++) xv[i] = xr4[lane + (i << 5)];

    // fused x -> fp16 store
    uint2* xh4 = reinterpret_cast<uint2*>(g_xh + (size_t)t * DD);
#pragma unroll
    for (int i = 0; i < 8; i++) {
        __half2 h0 = __floats2half2_rn(xv[i].x, xv[i].y);
        __half2 h1 = __floats2half2_rn(xv[i].z, xv[i].w);
        uint2 o;
        o.x = *reinterpret_cast<uint32_t*>(&h0);
        o.y = *reinterpret_cast<uint32_t*>(&h1);
        xh4[lane + (i << 5)] = o;
    }

    float logit[EE];
#pragma unroll
    for (int e = 0; e < EE; e++) {
        const float4* we4 = reinterpret_cast<const float4*>(rw + (size_t)e * DD);
        float acc = 0.0f;
#pragma unroll
        for (int i = 0; i < 8; i++) {
            float4 w4 = we4[lane + (i << 5)];
            acc += xv[i].x * w4.x + xv[i].y * w4.y + xv[i].z * w4.z + xv[i].w * w4.w;
        }
#pragma unroll
        for (int o = 16; o > 0; o >>= 1) acc += __shfl_xor_sync(0xffffffffu, acc, o);
        logit[e] = acc + bias[e];
    }

    if (lane == 0) {
        int e0 = 0;
#pragma unroll
        for (int e = 1; e < EE; e++) if (logit[e] > logit[e0]) e0 = e;
        int e1 = -1;
#pragma unroll
        for (int e = 0; e < EE; e++) {
            if (e == e0) continue;
            if (e1 < 0 || logit[e] > logit[e1]) e1 = e;
        }
        float l0 = logit[e0], l1 = logit[e1];
        float p1 = expf(l1 - l0);
        float inv = 1.0f / (1.0f + p1);
        float w0 = inv, w1 = p1 * inv;

        int pos0 = atomicAdd(&g_count[e0], 1);
        int pos1 = atomicAdd(&g_count[e1], 1);
        g_tok[e0 * TT + pos0] = t;
        g_tok[e1 * TT + pos1] = t;
        g_wt[e0 * TT + pos0] = w0;
        g_wt[e1 * TT + pos1] = w1;
    }
}

__global__ void offsets_kernel() {
    if (threadIdx.x == 0 && blockIdx.x == 0) {
        int a = 0;
        for (int e = 0; e < EE; e++) { g_offs[e] = a; a += g_count[e]; }
        g_offs[EE] = a;
    }
}

// ---------------------------------------------------------------------------
// GEMM1 (dual fp16): hidden = silu(X W1) * (X W3). CTA 128x64(dual), K32 stages,
// ldmatrix.x4 fragment loads, 4-stage cp.async ring.
// ---------------------------------------------------------------------------
#define A_OFF    0
#define A_WORDS  (128 * 20)
#define B1_OFF   A_WORDS
#define B1_WORDS (64 * 20)
#define B3_OFF   (B1_OFF + B1_WORDS)
#define STG1_WORDS (A_WORDS + 2 * B1_WORDS)
#define STG1_BYTES (STG1_WORDS * 4)
#define SMEM1_BYTES (4 * STG1_BYTES)        // 81920

__global__ __launch_bounds__(256, 2)
void gemm1_kernel() {
    extern __shared__ uint32_t smemw[];

    int g = blockIdx.z;
    int M, rowbase;
    const int* toks;
    const __half *W1H, *W3H;
    if (g < EE) {
        M = g_count[g]; rowbase = g_offs[g]; toks = g_tok + g * TT;
        W1H = g_w1h + (size_t)g * DD * HH; W3H = g_w3h + (size_t)g * DD * HH;
    } else {
        M = TT; rowbase = NMOE; toks = nullptr;
        W1H = g_sw1h; W3H = g_sw3h;
    }
    int bm0 = blockIdx.x * 128;
    if (bm0 >= M) return;
    int n0 = blockIdx.y * 64;

    int tid  = threadIdx.x;
    int lane = tid & 31, wid = tid >> 5;
    int wm = wid & 3, wn = wid >> 2;       // 4x2 warps -> 32x32 per warp (dual)
    int t4 = lane & 3, t8 = lane >> 2;

    float accG[2][4][4] = {}, accU[2][4][4] = {};

    // producer: 1024 chunks (A 512, B1 256, B3 256) -> 4 per thread
    const __half* src[4];
    int sz[4], off[4];
#pragma unroll
    for (int j = 0; j < 4; j++) {
        int c = tid + 256 * j;
        if (c < 512) {
            int row = c >> 2, kw = (c & 3) << 2;
            int gm = bm0 + row;
            if (gm < M) {
                int tr = toks ? toks[gm] : gm;
                src[j] = g_xh + (size_t)tr * DD + kw * 2; sz[j] = 16;
            } else { src[j] = g_xh; sz[j] = 0; }
            off[j] = A_OFF + row * 20 + kw;
        } else if (c < 768) {
            int n = (c - 512) >> 2, kw = (c & 3) << 2;
            src[j] = W1H + (size_t)(n0 + n) * DD + kw * 2; sz[j] = 16;
            off[j] = B1_OFF + n * 20 + kw;
        } else {
            int n = (c - 768) >> 2, kw = (c & 3) << 2;
            src[j] = W3H + (size_t)(n0 + n) * DD + kw * 2; sz[j] = 16;
            off[j] = B3_OFF + n * 20 + kw;
        }
    }

    uint32_t sbase = (uint32_t)__cvta_generic_to_shared(smemw);

    int awo[2];
#pragma unroll
    for (int mi = 0; mi < 2; mi++)
        awo[mi] = A_OFF + (wm * 32 + mi * 16 + (lane & 15)) * 20 + ((lane >> 4) << 2);
    int bwo1[2], bwo3[2];
#pragma unroll
    for (int p = 0; p < 2; p++) {
        int rowoff = (wn * 32 + p * 16 + ((lane >> 4) << 3) + (lane & 7)) * 20
                   + (((lane >> 3) & 1) << 2);
        bwo1[p] = B1_OFF + rowoff;
        bwo3[p] = B3_OFF + rowoff;
    }

#pragma unroll
    for (int p = 0; p < 2; p++) {
        uint32_t sb = sbase + p * STG1_BYTES;
        int k0 = p * 32;
#pragma unroll
        for (int j = 0; j < 4; j++) cp16(sb + off[j] * 4, src[j] + k0, sz[j]);
        cp_commit();
    }

    const int KB = DD / 32;
    for (int kb = 0; kb < KB; kb++) {
        if (kb + 2 < KB) {
            uint32_t sb = sbase + ((kb + 2) & 3) * STG1_BYTES;
            int k0 = (kb + 2) * 32;
#pragma unroll
            for (int j = 0; j < 4; j++) cp16(sb + off[j] * 4, src[j] + k0, sz[j]);
        }
        cp_commit();
        cp_wait2();
        __syncthreads();

        uint32_t stgb = sbase + (kb & 3) * STG1_BYTES;

#pragma unroll
        for (int ks = 0; ks < 2; ks++) {
            uint32_t kofs = stgb + ks * 32;
            uint32_t a[2][4], b1[2][4], b3[2][4];
            ldsm4(a[0],  kofs + awo[0] * 4);
            ldsm4(a[1],  kofs + awo[1] * 4);
            ldsm4(b1[0], kofs + bwo1[0] * 4);
            ldsm4(b1[1], kofs + bwo1[1] * 4);
            ldsm4(b3[0], kofs + bwo3[0] * 4);
            ldsm4(b3[1], kofs + bwo3[1] * 4);
#pragma unroll
            for (int mi = 0; mi < 2; mi++)
#pragma unroll
                for (int nj = 0; nj < 4; nj++) {
                    mma16(accG[mi][nj], a[mi], &b1[nj >> 1][(nj & 1) * 2]);
                    mma16(accU[mi][nj], a[mi], &b3[nj >> 1][(nj & 1) * 2]);
                }
        }
    }

    // epilogue: silu(G)*U -> g_hidden (fp16)
#pragma unroll
    for (int mi = 0; mi < 2; mi++) {
#pragma unroll
        for (int h = 0; h < 2; h++) {
            int row = wm * 32 + mi * 16 + t8 + h * 8;
            int grow = bm0 + row;
            if (grow < M) {
                size_t base = (size_t)(rowbase + grow) * HH + n0;
#pragma unroll
                for (int nj = 0; nj < 4; nj++) {
                    int col = wn * 32 + nj * 8 + t4 * 2;
                    float v0 = silu_f(accG[mi][nj][h * 2 + 0]) * accU[mi][nj][h * 2 + 0];
                    float v1 = silu_f(accG[mi][nj][h * 2 + 1]) * accU[mi][nj][h * 2 + 1];
                    __half2 hh = __floats2half2_rn(v0, v1);
                    *reinterpret_cast<__half2*>(&g_hidden[base + col]) = hh;
                }
            }
        }
    }
}

// ---------------------------------------------------------------------------
// GEMM2 (fp16): out += w * (hidden @ W2). CTA 128x128, warp 32x64, K32 stages,
// ldmatrix, fused weighted reduction epilogue (red.global.add.v2.f32).
// ---------------------------------------------------------------------------
#define B2_OFF   A_WORDS
#define B2_WORDS (128 * 20)
#define STG2_WORDS (A_WORDS + B2_WORDS)
#define STG2_BYTES (STG2_WORDS * 4)
#define SMEM2_BYTES (4 * STG2_BYTES)        // 81920

__global__ __launch_bounds__(256, 2)
void gemm2_kernel(float* __restrict__ out) {
    extern __shared__ uint32_t smemw[];

    int g = blockIdx.z;
    int M, rowbase;
    const int* toks;
    const float* wts;
    const __half* W2H;
    if (g < EE) {
        M = g_count[g]; rowbase = g_offs[g];
        toks = g_tok + g * TT; wts = g_wt + g * TT;
        W2H = g_w2h + (size_t)g * HH * DD;
    } else {
        M = TT; rowbase = NMOE; toks = nullptr; wts = nullptr;
        W2H = g_sw2h;
    }
    int bm0 = blockIdx.x * 128;
    if (bm0 >= M) return;
    int n0 = blockIdx.y * 128;

    int tid  = threadIdx.x;
    int lane = tid & 31, wid = tid >> 5;
    int wm = wid & 3, wn = wid >> 2;       // warp 32 x 64
    int t4 = lane & 3, t8 = lane >> 2;

    float acc[2][8][4] = {};

    const __half* src[4];
    int sz[4], off[4];
#pragma unroll
    for (int j = 0; j < 4; j++) {
        int c = tid + 256 * j;
        if (c < 512) {
            int row = c >> 2, kw = (c & 3) << 2;
            int gm = bm0 + row;
            if (gm < M) {
                src[j] = g_hidden + (size_t)(rowbase + gm) * HH + kw * 2; sz[j] = 16;
            } else { src[j] = g_hidden; sz[j] = 0; }
            off[j] = A_OFF + row * 20 + kw;
        } else {
            int n = (c - 512) >> 2, kw = (c & 3) << 2;
            src[j] = W2H + (size_t)(n0 + n) * HH + kw * 2; sz[j] = 16;
            off[j] = B2_OFF + n * 20 + kw;
        }
    }

    uint32_t sbase = (uint32_t)__cvta_generic_to_shared(smemw);

    int awo[2];
#pragma unroll
    for (int mi = 0; mi < 2; mi++)
        awo[mi] = A_OFF + (wm * 32 + mi * 16 + (lane & 15)) * 20 + ((lane >> 4) << 2);
    int bwo[4];
#pragma unroll
    for (int p = 0; p < 4; p++) {
        bwo[p] = B2_OFF + (wn * 64 + p * 16 + ((lane >> 4) << 3) + (lane & 7)) * 20
               + (((lane >> 3) & 1) << 2);
    }

#pragma unroll
    for (int p = 0; p < 2; p++) {
        uint32_t sb = sbase + p * STG2_BYTES;
        int k0 = p * 32;
#pragma unroll
        for (int j = 0; j < 4; j++) cp16(sb + off[j] * 4, src[j] + k0, sz[j]);
        cp_commit();
    }

    const int KB = HH / 32;
    for (int kb = 0; kb < KB; kb++) {
        if (kb + 2 < KB) {
            uint32_t sb = sbase + ((kb + 2) & 3) * STG2_BYTES;
            int k0 = (kb + 2) * 32;
#pragma unroll
            for (int j = 0; j < 4; j++) cp16(sb + off[j] * 4, src[j] + k0, sz[j]);
        }
        cp_commit();
        cp_wait2();
        __syncthreads();

        uint32_t stgb = sbase + (kb & 3) * STG2_BYTES;

#pragma unroll
        for (int ks = 0; ks < 2; ks++) {
            uint32_t kofs = stgb + ks * 32;
            uint32_t a[2][4], bb[4][4];
            ldsm4(a[0], kofs + awo[0] * 4);
            ldsm4(a[1], kofs + awo[1] * 4);
#pragma unroll
            for (int p = 0; p < 4; p++) ldsm4(bb[p], kofs + bwo[p] * 4);
#pragma unroll
            for (int mi = 0; mi < 2; mi++)
#pragma unroll
                for (int nj = 0; nj < 8; nj++)
                    mma16(acc[mi][nj], a[mi], &bb[nj >> 1][(nj & 1) * 2]);
        }
    }

    // epilogue: weighted atomic reduction into out
#pragma unroll
    for (int mi = 0; mi < 2; mi++) {
#pragma unroll
        for (int h = 0; h < 2; h++) {
            int row = wm * 32 + mi * 16 + t8 + h * 8;
            int grow = bm0 + row;
            if (grow < M) {
                int tok;
                float w;
                if (g < EE) { tok = toks[grow]; w = wts[grow]; }
                else        { tok = grow;       w = 1.0f; }
                float* obase = out + (size_t)tok * DD + n0;
#pragma unroll
                for (int nj = 0; nj < 8; nj++) {
                    int col = wn * 64 + nj * 8 + t4 * 2;
                    red2(obase + col,
                         w * acc[mi][nj][h * 2 + 0],
                         w * acc[mi][nj][h * 2 + 1]);
                }
            }
        }
    }
}

// ---------------------------------------------------------------------------
// Launch
// ---------------------------------------------------------------------------
extern "C" void kernel_launch(void* const* d_in, const int* in_sizes, int n_in,
                              void* d_out, int out_size) {
    const float* x    = (const float*)d_in[0];
    const float* rw   = (const float*)d_in[1];
    const float* bias = (const float*)d_in[2];
    const float* w1   = (const float*)d_in[3];
    const float* w3   = (const float*)d_in[4];
    const float* w2   = (const float*)d_in[5];
    const float* sw1  = (const float*)d_in[6];
    const float* sw3  = (const float*)d_in[7];
    const float* sw2  = (const float*)d_in[8];
    float* out = (float*)d_out;

    cudaFuncSetAttribute(gemm1_kernel, cudaFuncAttributeMaxDynamicSharedMemorySize, SMEM1_BYTES);
    cudaFuncSetAttribute(gemm2_kernel, cudaFuncAttributeMaxDynamicSharedMemorySize, SMEM2_BYTES);

    __half* w1h;  cudaGetSymbolAddress((void**)&w1h, g_w1h);
    __half* w3h;  cudaGetSymbolAddress((void**)&w3h, g_w3h);
    __half* w2h;  cudaGetSymbolAddress((void**)&w2h, g_w2h);
    __half* s1h;  cudaGetSymbolAddress((void**)&s1h, g_sw1h);
    __half* s3h;  cudaGetSymbolAddress((void**)&s3h, g_sw3h);
    __half* s2h;  cudaGetSymbolAddress((void**)&s2h, g_sw2h);

    // out := 0 (required for the fused reduction epilogue; out is poisoned)
    zero_out_kernel<<<(int)(XSZ / 1024), 256>>>((float4*)out);

    // weights: batched transpose + fp16 convert
    {
        dim3 g1(HH / 32, DD / 32, 2 * EE + 2);
        trans_cvt_f1<<<g1, 256>>>(w1, w3, sw1, sw3, w1h, w3h, s1h, s3h);
        dim3 g2(DD / 32, HH / 32, EE + 1);
        trans_cvt_f2<<<g2, 256>>>(w2, sw2, w2h, s2h);
    }

    zero_counts_kernel<<<1, 32>>>();
    router_kernel<<<TT / 8, 256>>>(x, rw, bias);   // also emits g_xh (fp16)
    offsets_kernel<<<1, 32>>>();

    dim3 grid1(TT / 128, HH / 64, EE + 1);       // (64, 32, 9)
    gemm1_kernel<<<grid1, 256, SMEM1_BYTES>>>();

    dim3 grid2(TT / 128, DD / 128, EE + 1);      // (64, 8, 9)
    gemm2_kernel<<<grid2, 256, SMEM2_BYTES>>>(out);
}

// round 16
// speedup vs baseline: 2.2002x; 1.0855x over previous
#include <cuda_runtime.h>
#include <cuda_fp16.h>
#include <math.h>
#include <stdint.h>

// Problem constants
#define DD   1024
#define HH   2048
#define EE   8
#define TT   8192
#define KTOP 2
#define NMOE (TT * KTOP)
#define NROWS (NMOE + TT)

#define XSZ   ((size_t)TT * DD)
#define WSZ   ((size_t)EE * DD * HH)
#define SWSZ  ((size_t)DD * HH)

// ---------------------------------------------------------------------------
// Scratch (static __device__ globals)
// ---------------------------------------------------------------------------
__device__ __half g_hidden[(size_t)NROWS * HH];   // fp16 activations
__device__ __half g_xh[XSZ];                      // x fp16, [T][D] (written by router)
__device__ __half g_w1h[WSZ];                     // W1^T fp16: [E][H][D]
__device__ __half g_w3h[WSZ];
__device__ __half g_w2h[WSZ];                     // W2^T fp16: [E][D][H]
__device__ __half g_sw1h[SWSZ];
__device__ __half g_sw3h[SWSZ];
__device__ __half g_sw2h[SWSZ];
__device__ int   g_count[EE];
__device__ int   g_tok[EE * TT];                  // per-expert token lists
__device__ float g_wt[EE * TT];                   // per-expert combine weights (by pos)

// ---------------------------------------------------------------------------
// Helpers
// ---------------------------------------------------------------------------
__device__ __forceinline__ void mma16(float c[4], const uint32_t a[4], const uint32_t* b) {
    asm volatile(
        "mma.sync.aligned.m16n8k16.row.col.f32.f16.f16.f32 "
        "{%0,%1,%2,%3},{%4,%5,%6,%7},{%8,%9},{%0,%1,%2,%3};\n"
        : "+f"(c[0]), "+f"(c[1]), "+f"(c[2]), "+f"(c[3])
        : "r"(a[0]), "r"(a[1]), "r"(a[2]), "r"(a[3]), "r"(b[0]), "r"(b[1]));
}

__device__ __forceinline__ void ldsm4(uint32_t r[4], uint32_t addr) {
    asm volatile("ldmatrix.sync.aligned.m8n8.x4.shared.b16 {%0,%1,%2,%3}, [%4];"
                 : "=r"(r[0]), "=r"(r[1]), "=r"(r[2]), "=r"(r[3]) : "r"(addr));
}

// L2-only (bypass L1): GEMM operands have zero intra-CTA reuse.
__device__ __forceinline__ void cp16(uint32_t smem_dst, const void* gmem_src, int src_size) {
    asm volatile("cp.async.cg.shared.global [%0], [%1], 16, %2;"
                 :: "r"(smem_dst), "l"(gmem_src), "r"(src_size));
}
__device__ __forceinline__ void cp_commit() { asm volatile("cp.async.commit_group;"); }
__device__ __forceinline__ void cp_wait2()  { asm volatile("cp.async.wait_group 2;" ::: "memory"); }

__device__ __forceinline__ void red2(float* ptr, float v0, float v1) {
    asm volatile("red.global.add.v2.f32 [%0], {%1, %2};"
                 :: "l"(ptr), "f"(v0), "f"(v1) : "memory");
}

__device__ __forceinline__ float silu_f(float v) { return v / (1.0f + __expf(-v)); }

// per-CTA prefix over g_count: rowbase of group g (g == EE -> NMOE)
__device__ __forceinline__ void group_range(int g, int& M, int& rowbase) {
    if (g >= EE) { M = TT; rowbase = NMOE; return; }
    int rb = 0;
#pragma unroll
    for (int e = 0; e < EE; e++) {
        int c = g_count[e];
        if (e < g) rb += c;
        if (e == g) M = c;
    }
    rowbase = rb;
}

// ---------------------------------------------------------------------------
// Prep: batched transpose+convert for the [D][H] family (w1, w3, sw1, sw3)
// ---------------------------------------------------------------------------
__global__ void trans_cvt_f1(const float* __restrict__ w1, const float* __restrict__ w3,
                             const float* __restrict__ sw1, const float* __restrict__ sw3,
                             __half* __restrict__ d1, __half* __restrict__ d3,
                             __half* __restrict__ ds1, __half* __restrict__ ds3) {
    const int K = DD, N = HH;
    int z = blockIdx.z;
    const float* src;
    __half* dst;
    if (z < EE)            { src = w1  + (size_t)z * K * N;        dst = d1  + (size_t)z * K * N; }
    else if (z < 2 * EE)   { src = w3  + (size_t)(z - EE) * K * N; dst = d3  + (size_t)(z - EE) * K * N; }
    else if (z == 2 * EE)  { src = sw1;                            dst = ds1; }
    else                   { src = sw3;                            dst = ds3; }

    __shared__ float t[32][33];
    int n0 = blockIdx.x * 32, k0 = blockIdx.y * 32;
    int tx = threadIdx.x & 31, ty = threadIdx.x >> 5;
#pragma unroll
    for (int i = 0; i < 4; i++)
        t[ty + 8 * i][tx] = src[(size_t)(k0 + ty + 8 * i) * N + n0 + tx];
    __syncthreads();
#pragma unroll
    for (int i = 0; i < 4; i++)
        dst[(size_t)(n0 + ty + 8 * i) * K + k0 + tx] = __float2half_rn(t[tx][ty + 8 * i]);
}

// [H][D] family (w2, sw2)
__global__ void trans_cvt_f2(const float* __restrict__ w2, const float* __restrict__ sw2,
                             __half* __restrict__ d2, __half* __restrict__ ds2) {
    const int K = HH, N = DD;
    int z = blockIdx.z;
    const float* src = (z < EE) ? (w2 + (size_t)z * K * N) : sw2;
    __half* dst      = (z < EE) ? (d2 + (size_t)z * K * N) : ds2;

    __shared__ float t[32][33];
    int n0 = blockIdx.x * 32, k0 = blockIdx.y * 32;
    int tx = threadIdx.x & 31, ty = threadIdx.x >> 5;
#pragma unroll
    for (int i = 0; i < 4; i++)
        t[ty + 8 * i][tx] = src[(size_t)(k0 + ty + 8 * i) * N + n0 + tx];
    __syncthreads();
#pragma unroll
    for (int i = 0; i < 4; i++)
        dst[(size_t)(n0 + ty + 8 * i) * K + k0 + tx] = __float2half_rn(t[tx][ty + 8 * i]);
}

// ---------------------------------------------------------------------------
// zero kernel: out := 0, and block 0 also resets the expert counters
// ---------------------------------------------------------------------------
__global__ void zero_out_kernel(float4* __restrict__ out) {
    int i = blockIdx.x * blockDim.x + threadIdx.x;
    out[i] = make_float4(0.f, 0.f, 0.f, 0.f);
    if (blockIdx.x == 0 && threadIdx.x < EE) g_count[threadIdx.x] = 0;
}

// ---------------------------------------------------------------------------
// Router: logits + top-2 + token lists; also emits x in fp16 (fused convert).
// ---------------------------------------------------------------------------
__global__ void router_kernel(const float* __restrict__ x, const float* __restrict__ rw,
                              const float* __restrict__ bias) {
    int warp = threadIdx.x >> 5;
    int lane = threadIdx.x & 31;
    int t = blockIdx.x * 8 + warp;

    const float4* xr4 = reinterpret_cast<const float4*>(x + (size_t)t * DD);
    float4 xv[8];
#pragma unroll
    for (int i = 0; i < 8; i++) xv[i] = xr4[lane + (i << 5)];

    // fused x -> fp16 store
    uint2* xh4 = reinterpret_cast<uint2*>(g_xh + (size_t)t * DD);
#pragma unroll
    for (int i = 0; i < 8; i++) {
        __half2 h0 = __floats2half2_rn(xv[i].x, xv[i].y);
        __half2 h1 = __floats2half2_rn(xv[i].z, xv[i].w);
        uint2 o;
        o.x = *reinterpret_cast<uint32_t*>(&h0);
        o.y = *reinterpret_cast<uint32_t*>(&h1);
        xh4[lane + (i << 5)] = o;
    }

    float logit[EE];
#pragma unroll
    for (int e = 0; e < EE; e++) {
        const float4* we4 = reinterpret_cast<const float4*>(rw + (size_t)e * DD);
        float acc = 0.0f;
#pragma unroll
        for (int i = 0; i < 8; i++) {
            float4 w4 = we4[lane + (i << 5)];
            acc += xv[i].x * w4.x + xv[i].y * w4.y + xv[i].z * w4.z + xv[i].w * w4.w;
        }
#pragma unroll
        for (int o = 16; o > 0; o >>= 1) acc += __shfl_xor_sync(0xffffffffu, acc, o);
        logit[e] = acc + bias[e];
    }

    if (lane == 0) {
        int e0 = 0;
#pragma unroll
        for (int e = 1; e < EE; e++) if (logit[e] > logit[e0]) e0 = e;
        int e1 = -1;
#pragma unroll
        for (int e = 0; e < EE; e++) {
            if (e == e0) continue;
            if (e1 < 0 || logit[e] > logit[e1]) e1 = e;
        }
        float l0 = logit[e0], l1 = logit[e1];
        float p1 = expf(l1 - l0);
        float inv = 1.0f / (1.0f + p1);
        float w0 = inv, w1 = p1 * inv;

        int pos0 = atomicAdd(&g_count[e0], 1);
        int pos1 = atomicAdd(&g_count[e1], 1);
        g_tok[e0 * TT + pos0] = t;
        g_tok[e1 * TT + pos1] = t;
        g_wt[e0 * TT + pos0] = w0;
        g_wt[e1 * TT + pos1] = w1;
    }
}

// ---------------------------------------------------------------------------
// GEMM1 (dual fp16): hidden = silu(X W1) * (X W3). CTA 128x64(dual), K32 stages,
// ldmatrix.x4 fragment loads, 4-stage cp.async ring.
// ---------------------------------------------------------------------------
#define A_OFF    0
#define A_WORDS  (128 * 20)
#define B1_OFF   A_WORDS
#define B1_WORDS (64 * 20)
#define B3_OFF   (B1_OFF + B1_WORDS)
#define STG1_WORDS (A_WORDS + 2 * B1_WORDS)
#define STG1_BYTES (STG1_WORDS * 4)
#define SMEM1_BYTES (4 * STG1_BYTES)        // 81920

__global__ __launch_bounds__(256, 2)
void gemm1_kernel() {
    extern __shared__ uint32_t smemw[];

    int g = blockIdx.z;
    int M, rowbase;
    group_range(g, M, rowbase);
    const int* toks = (g < EE) ? (g_tok + g * TT) : nullptr;
    const __half *W1H, *W3H;
    if (g < EE) {
        W1H = g_w1h + (size_t)g * DD * HH; W3H = g_w3h + (size_t)g * DD * HH;
    } else {
        W1H = g_sw1h; W3H = g_sw3h;
    }
    int bm0 = blockIdx.x * 128;
    if (bm0 >= M) return;
    int n0 = blockIdx.y * 64;

    int tid  = threadIdx.x;
    int lane = tid & 31, wid = tid >> 5;
    int wm = wid & 3, wn = wid >> 2;       // 4x2 warps -> 32x32 per warp (dual)
    int t4 = lane & 3, t8 = lane >> 2;

    float accG[2][4][4] = {}, accU[2][4][4] = {};

    // producer: 1024 chunks (A 512, B1 256, B3 256) -> 4 per thread
    const __half* src[4];
    int sz[4], off[4];
#pragma unroll
    for (int j = 0; j < 4; j++) {
        int c = tid + 256 * j;
        if (c < 512) {
            int row = c >> 2, kw = (c & 3) << 2;
            int gm = bm0 + row;
            if (gm < M) {
                int tr = toks ? toks[gm] : gm;
                src[j] = g_xh + (size_t)tr * DD + kw * 2; sz[j] = 16;
            } else { src[j] = g_xh; sz[j] = 0; }
            off[j] = A_OFF + row * 20 + kw;
        } else if (c < 768) {
            int n = (c - 512) >> 2, kw = (c & 3) << 2;
            src[j] = W1H + (size_t)(n0 + n) * DD + kw * 2; sz[j] = 16;
            off[j] = B1_OFF + n * 20 + kw;
        } else {
            int n = (c - 768) >> 2, kw = (c & 3) << 2;
            src[j] = W3H + (size_t)(n0 + n) * DD + kw * 2; sz[j] = 16;
            off[j] = B3_OFF + n * 20 + kw;
        }
    }

    uint32_t sbase = (uint32_t)__cvta_generic_to_shared(smemw);

    int awo[2];
#pragma unroll
    for (int mi = 0; mi < 2; mi++)
        awo[mi] = A_OFF + (wm * 32 + mi * 16 + (lane & 15)) * 20 + ((lane >> 4) << 2);
    int bwo1[2], bwo3[2];
#pragma unroll
    for (int p = 0; p < 2; p++) {
        int rowoff = (wn * 32 + p * 16 + ((lane >> 4) << 3) + (lane & 7)) * 20
                   + (((lane >> 3) & 1) << 2);
        bwo1[p] = B1_OFF + rowoff;
        bwo3[p] = B3_OFF + rowoff;
    }

#pragma unroll
    for (int p = 0; p < 2; p++) {
        uint32_t sb = sbase + p * STG1_BYTES;
        int k0 = p * 32;
#pragma unroll
        for (int j = 0; j < 4; j++) cp16(sb + off[j] * 4, src[j] + k0, sz[j]);
        cp_commit();
    }

    const int KB = DD / 32;
    for (int kb = 0; kb < KB; kb++) {
        if (kb + 2 < KB) {
            uint32_t sb = sbase + ((kb + 2) & 3) * STG1_BYTES;
            int k0 = (kb + 2) * 32;
#pragma unroll
            for (int j = 0; j < 4; j++) cp16(sb + off[j] * 4, src[j] + k0, sz[j]);
        }
        cp_commit();
        cp_wait2();
        __syncthreads();

        uint32_t stgb = sbase + (kb & 3) * STG1_BYTES;

#pragma unroll
        for (int ks = 0; ks < 2; ks++) {
            uint32_t kofs = stgb + ks * 32;
            uint32_t a[2][4], b1[2][4], b3[2][4];
            ldsm4(a[0],  kofs + awo[0] * 4);
            ldsm4(a[1],  kofs + awo[1] * 4);
            ldsm4(b1[0], kofs + bwo1[0] * 4);
            ldsm4(b1[1], kofs + bwo1[1] * 4);
            ldsm4(b3[0], kofs + bwo3[0] * 4);
            ldsm4(b3[1], kofs + bwo3[1] * 4);
#pragma unroll
            for (int mi = 0; mi < 2; mi++)
#pragma unroll
                for (int nj = 0; nj < 4; nj++) {
                    mma16(accG[mi][nj], a[mi], &b1[nj >> 1][(nj & 1) * 2]);
                    mma16(accU[mi][nj], a[mi], &b3[nj >> 1][(nj & 1) * 2]);
                }
        }
    }

    // epilogue: silu(G)*U -> g_hidden (fp16)
#pragma unroll
    for (int mi = 0; mi < 2; mi++) {
#pragma unroll
        for (int h = 0; h < 2; h++) {
            int row = wm * 32 + mi * 16 + t8 + h * 8;
            int grow = bm0 + row;
            if (grow < M) {
                size_t base = (size_t)(rowbase + grow) * HH + n0;
#pragma unroll
                for (int nj = 0; nj < 4; nj++) {
                    int col = wn * 32 + nj * 8 + t4 * 2;
                    float v0 = silu_f(accG[mi][nj][h * 2 + 0]) * accU[mi][nj][h * 2 + 0];
                    float v1 = silu_f(accG[mi][nj][h * 2 + 1]) * accU[mi][nj][h * 2 + 1];
                    __half2 hh = __floats2half2_rn(v0, v1);
                    *reinterpret_cast<__half2*>(&g_hidden[base + col]) = hh;
                }
            }
        }
    }
}

// ---------------------------------------------------------------------------
// GEMM2 (fp16): out += w * (hidden @ W2). CTA 128x128, warp 32x64, K32 stages,
// ldmatrix, fused weighted reduction epilogue.
// ---------------------------------------------------------------------------
#define B2_OFF   A_WORDS
#define B2_WORDS (128 * 20)
#define STG2_WORDS (A_WORDS + B2_WORDS)
#define STG2_BYTES (STG2_WORDS * 4)
#define SMEM2_BYTES (4 * STG2_BYTES)        // 81920

__global__ __launch_bounds__(256, 2)
void gemm2_kernel(float* __restrict__ out) {
    extern __shared__ uint32_t smemw[];

    int g = blockIdx.z;
    int M, rowbase;
    group_range(g, M, rowbase);
    const int* toks  = (g < EE) ? (g_tok + g * TT) : nullptr;
    const float* wts = (g < EE) ? (g_wt + g * TT) : nullptr;
    const __half* W2H = (g < EE) ? (g_w2h + (size_t)g * HH * DD) : g_sw2h;

    int bm0 = blockIdx.x * 128;
    if (bm0 >= M) return;
    int n0 = blockIdx.y * 128;

    int tid  = threadIdx.x;
    int lane = tid & 31, wid = tid >> 5;
    int wm = wid & 3, wn = wid >> 2;       // warp 32 x 64
    int t4 = lane & 3, t8 = lane >> 2;

    float acc[2][8][4] = {};

    const __half* src[4];
    int sz[4], off[4];
#pragma unroll
    for (int j = 0; j < 4; j++) {
        int c = tid + 256 * j;
        if (c < 512) {
            int row = c >> 2, kw = (c & 3) << 2;
            int gm = bm0 + row;
            if (gm < M) {
                src[j] = g_hidden + (size_t)(rowbase + gm) * HH + kw * 2; sz[j] = 16;
            } else { src[j] = g_hidden; sz[j] = 0; }
            off[j] = A_OFF + row * 20 + kw;
        } else {
            int n = (c - 512) >> 2, kw = (c & 3) << 2;
            src[j] = W2H + (size_t)(n0 + n) * HH + kw * 2; sz[j] = 16;
            off[j] = B2_OFF + n * 20 + kw;
        }
    }

    uint32_t sbase = (uint32_t)__cvta_generic_to_shared(smemw);

    int awo[2];
#pragma unroll
    for (int mi = 0; mi < 2; mi++)
        awo[mi] = A_OFF + (wm * 32 + mi * 16 + (lane & 15)) * 20 + ((lane >> 4) << 2);
    int bwo[4];
#pragma unroll
    for (int p = 0; p < 4; p++) {
        bwo[p] = B2_OFF + (wn * 64 + p * 16 + ((lane >> 4) << 3) + (lane & 7)) * 20
               + (((lane >> 3) & 1) << 2);
    }

#pragma unroll
    for (int p = 0; p < 2; p++) {
        uint32_t sb = sbase + p * STG2_BYTES;
        int k0 = p * 32;
#pragma unroll
        for (int j = 0; j < 4; j++) cp16(sb + off[j] * 4, src[j] + k0, sz[j]);
        cp_commit();
    }

    const int KB = HH / 32;
    for (int kb = 0; kb < KB; kb++) {
        if (kb + 2 < KB) {
            uint32_t sb = sbase + ((kb + 2) & 3) * STG2_BYTES;
            int k0 = (kb + 2) * 32;
#pragma unroll
            for (int j = 0; j < 4; j++) cp16(sb + off[j] * 4, src[j] + k0, sz[j]);
        }
        cp_commit();
        cp_wait2();
        __syncthreads();

        uint32_t stgb = sbase + (kb & 3) * STG2_BYTES;

#pragma unroll
        for (int ks = 0; ks < 2; ks++) {
            uint32_t kofs = stgb + ks * 32;
            uint32_t a[2][4], bb[4][4];
            ldsm4(a[0], kofs + awo[0] * 4);
            ldsm4(a[1], kofs + awo[1] * 4);
#pragma unroll
            for (int p = 0; p < 4; p++) ldsm4(bb[p], kofs + bwo[p] * 4);
#pragma unroll
            for (int mi = 0; mi < 2; mi++)
#pragma unroll
                for (int nj = 0; nj < 8; nj++)
                    mma16(acc[mi][nj], a[mi], &bb[nj >> 1][(nj & 1) * 2]);
        }
    }

    // epilogue: weighted atomic reduction into out
#pragma unroll
    for (int mi = 0; mi < 2; mi++) {
#pragma unroll
        for (int h = 0; h < 2; h++) {
            int row = wm * 32 + mi * 16 + t8 + h * 8;
            int grow = bm0 + row;
            if (grow < M) {
                int tok;
                float w;
                if (g < EE) { tok = toks[grow]; w = wts[grow]; }
                else        { tok = grow;       w = 1.0f; }
                float* obase = out + (size_t)tok * DD + n0;
#pragma unroll
                for (int nj = 0; nj < 8; nj++) {
                    int col = wn * 64 + nj * 8 + t4 * 2;
                    red2(obase + col,
                         w * acc[mi][nj][h * 2 + 0],
                         w * acc[mi][nj][h * 2 + 1]);
                }
            }
        }
    }
}

// ---------------------------------------------------------------------------
// Launch
// ---------------------------------------------------------------------------
extern "C" void kernel_launch(void* const* d_in, const int* in_sizes, int n_in,
                              void* d_out, int out_size) {
    const float* x    = (const float*)d_in[0];
    const float* rw   = (const float*)d_in[1];
    const float* bias = (const float*)d_in[2];
    const float* w1   = (const float*)d_in[3];
    const float* w3   = (const float*)d_in[4];
    const float* w2   = (const float*)d_in[5];
    const float* sw1  = (const float*)d_in[6];
    const float* sw3  = (const float*)d_in[7];
    const float* sw2  = (const float*)d_in[8];
    float* out = (float*)d_out;

    cudaFuncSetAttribute(gemm1_kernel, cudaFuncAttributeMaxDynamicSharedMemorySize, SMEM1_BYTES);
    cudaFuncSetAttribute(gemm2_kernel, cudaFuncAttributeMaxDynamicSharedMemorySize, SMEM2_BYTES);

    __half* w1h;  cudaGetSymbolAddress((void**)&w1h, g_w1h);
    __half* w3h;  cudaGetSymbolAddress((void**)&w3h, g_w3h);
    __half* w2h;  cudaGetSymbolAddress((void**)&w2h, g_w2h);
    __half* s1h;  cudaGetSymbolAddress((void**)&s1h, g_sw1h);
    __half* s3h;  cudaGetSymbolAddress((void**)&s3h, g_sw3h);
    __half* s2h;  cudaGetSymbolAddress((void**)&s2h, g_sw2h);

    // out := 0 + reset expert counters (fused)
    zero_out_kernel<<<(int)(XSZ / 1024), 256>>>((float4*)out);

    // weights: batched transpose + fp16 convert
    {
        dim3 g1(HH / 32, DD / 32, 2 * EE + 2);
        trans_cvt_f1<<<g1, 256>>>(w1, w3, sw1, sw3, w1h, w3h, s1h, s3h);
        dim3 g2(DD / 32, HH / 32, EE + 1);
        trans_cvt_f2<<<g2, 256>>>(w2, sw2, w2h, s2h);
    }

    router_kernel<<<TT / 8, 256>>>(x, rw, bias);   // also emits g_xh (fp16)

    dim3 grid1(TT / 128, HH / 64, EE + 1);       // (64, 32, 9)
    gemm1_kernel<<<grid1, 256, SMEM1_BYTES>>>();

    dim3 grid2(TT / 128, DD / 128, EE + 1);      // (64, 8, 9)
    gemm2_kernel<<<grid2, 256, SMEM2_BYTES>>>(out);
}